// round 8
// baseline (speedup 1.0000x reference)
#include <cuda_runtime.h>
#include <cmath>

#define NB   128
#define LSEQ 160
#define EMB  512
#define HE   512
#define HD   1024
#define TT   128
#define NGATE 4096
#define GRID 128

// ---------------- scratch ----------------
static __device__ float g_GBUF[(size_t)LSEQ * NB * NGATE];   // input-proj gates (PERMUTED cols)
static __device__ float g_H1 [(size_t)LSEQ * NB * (2 * HE)];
static __device__ float g_ENC[(size_t)LSEQ * NB * (2 * HE)];
static __device__ float g_henc[2][2 * NB * HE];              // encoder h, ping-pong
static __device__ float g_hraw[NB * HD];                     // decoder raw h_t (logits input)
static __device__ float g_hsum[2][NB * HD];                  // decoder h_{t-1}+enc_t, ping-pong
static __device__ __align__(128) int   g_previdx[NB];
static __device__ __align__(128) float g_loss;

// ---- distributed grid barrier state (each element on its own 128B line) ----
static __device__ __align__(128) unsigned g_cnt[8 * 32];     // 8 arrival counters
static __device__ __align__(128) unsigned g_lvl2[32];        // level-2 counter
static __device__ __align__(128) unsigned g_phaseA[16 * 32]; // 16 broadcast phase copies

__device__ __forceinline__ float sigm(float x) { return 1.0f / (1.0f + expf(-x)); }

// tf32 helpers: exact-ish fp32 GEMM via 3-term split
__device__ __forceinline__ unsigned tf32_of(float x) {
    unsigned u; asm("cvt.rna.tf32.f32 %0, %1;" : "=r"(u) : "f"(x)); return u;
}
__device__ __forceinline__ void tf32_split(float x, unsigned& hi, unsigned& lo) {
    hi = tf32_of(x);
    lo = tf32_of(x - __uint_as_float(hi));
}
__device__ __forceinline__ void mma8(float* c, unsigned a0, unsigned a1, unsigned a2, unsigned a3,
                                     unsigned b0, unsigned b1) {
    asm volatile("mma.sync.aligned.m16n8k8.row.col.f32.tf32.tf32.f32 "
                 "{%0,%1,%2,%3}, {%4,%5,%6,%7}, {%8,%9}, {%0,%1,%2,%3};"
                 : "+f"(c[0]), "+f"(c[1]), "+f"(c[2]), "+f"(c[3])
                 : "r"(a0), "r"(a1), "r"(a2), "r"(a3), "r"(b0), "r"(b1));
}

// Tree grid barrier. epoch values are monotonic (persist across kernels/replays).
// Arrivals: 8 padded counters (16 CTAs each). CTA0 threads 0-7 detect level-1,
// funnel into one level-2 counter; thread 0 broadcasts the new phase to 16
// padded read-only flag lines (8 polling CTAs per line).
__device__ __forceinline__ void sync_grid(unsigned ep)
{
    __syncthreads();
    int tid = threadIdx.x, bid = blockIdx.x;
    if (bid == 0) {
        if (tid == 0)
            asm volatile("red.release.gpu.add.u32 [%0], 1;" :: "l"(&g_cnt[0]) : "memory");
        if (tid < 8) {
            unsigned tgt = ep * 16u, v;
            do {
                asm volatile("ld.acquire.gpu.u32 %0, [%1];"
                             : "=r"(v) : "l"(&g_cnt[tid * 32]) : "memory");
            } while ((int)(v - tgt) < 0);
            asm volatile("red.release.gpu.add.u32 [%0], 1;" :: "l"(&g_lvl2[0]) : "memory");
        }
        if (tid == 0) {
            unsigned tgt2 = ep * 8u, v;
            do {
                asm volatile("ld.acquire.gpu.u32 %0, [%1];"
                             : "=r"(v) : "l"(&g_lvl2[0]) : "memory");
            } while ((int)(v - tgt2) < 0);
#pragma unroll
            for (int i = 0; i < 16; i++)
                asm volatile("st.release.gpu.u32 [%0], %1;"
                             :: "l"(&g_phaseA[i * 32]), "r"(ep) : "memory");
        }
    } else if (tid == 0) {
        asm volatile("red.release.gpu.add.u32 [%0], 1;"
                     :: "l"(&g_cnt[(bid & 7) * 32]) : "memory");
        const unsigned* flag = &g_phaseA[((bid >> 3) & 15) * 32];
        unsigned v, slp = 128;
        int miss = 0;
        for (;;) {
            asm volatile("ld.acquire.gpu.u32 %0, [%1];" : "=r"(v) : "l"(flag) : "memory");
            if ((int)(v - ep) >= 0) break;
            if (++miss > 4) { __nanosleep(slp); if (slp < 2048) slp <<= 1; }
        }
    }
    __syncthreads();
}

__device__ __forceinline__ unsigned epoch_init()
{
    unsigned p;
    asm volatile("ld.relaxed.gpu.u32 %0, [%1];" : "=r"(p) : "l"(&g_phaseA[0]) : "memory");
    return p + 1;
}

// permuted-col map (encoder, per 2048-col dir block):
// p = jblk*32 + gate*8 + jj  <->  natural = gate*512 + jblk*8 + jj

// ---------------- input-projection GEMM (tf32x3 mma), writes PERMUTED gate cols ----------------
template <int GATHER, int K>
__global__ __launch_bounds__(256) void inproj_gemm(
    const float* __restrict__ W, const float* __restrict__ bias,
    const float* __restrict__ embed, const int* __restrict__ ids)
{
    __shared__ float sA[128 * 20];
    __shared__ float sB[128 * 20];
    __shared__ int   rowoff[128];
    __shared__ int   natrow[128];
    __shared__ float sBias[128];
    int tid = threadIdx.x;
    int row0 = blockIdx.y * 128;
    int col0 = blockIdx.x * 128;
    if (tid < 128) {
        int p = col0 + tid;
        int dir = p >> 11;
        int q = p & 2047;
        int nat = dir * 2048 + ((q >> 3) & 3) * 512 + (q >> 5) * 8 + (q & 7);
        natrow[tid] = nat;
        sBias[tid] = bias[nat];
        if (GATHER) {
            int m = row0 + tid;
            rowoff[tid] = ids[(m & (NB - 1)) * LSEQ + (m >> 7)] * EMB;
        }
    }
    __syncthreads();
    int lane = tid & 31, w = tid >> 5;
    int wm = w >> 2, wn = w & 3;
    float acc[4][4][4];
#pragma unroll
    for (int a = 0; a < 4; a++)
#pragma unroll
        for (int b = 0; b < 4; b++)
#pragma unroll
            for (int c = 0; c < 4; c++) acc[a][b][c] = 0.f;

    for (int k0 = 0; k0 < K; k0 += 16) {
#pragma unroll
        for (int p = 0; p < 8; p++) {
            int idx = tid + p * 256;
            int r = idx >> 4, c = idx & 15;
            float v;
            if (GATHER) v = embed[rowoff[r] + k0 + c];
            else        v = g_H1[(size_t)(row0 + r) * K + k0 + c];
            sA[r * 20 + c] = v;
            sB[r * 20 + c] = W[(size_t)natrow[r] * K + k0 + c];
        }
        __syncthreads();
#pragma unroll
        for (int kk = 0; kk < 16; kk += 8) {
            unsigned ah[4][4], al[4][4];
#pragma unroll
            for (int mf = 0; mf < 4; mf++) {
                int ar = wm * 64 + mf * 16 + (lane >> 2);
                int ac = kk + (lane & 3);
                tf32_split(sA[ar * 20 + ac],           ah[mf][0], al[mf][0]);
                tf32_split(sA[(ar + 8) * 20 + ac],     ah[mf][1], al[mf][1]);
                tf32_split(sA[ar * 20 + ac + 4],       ah[mf][2], al[mf][2]);
                tf32_split(sA[(ar + 8) * 20 + ac + 4], ah[mf][3], al[mf][3]);
            }
#pragma unroll
            for (int nf = 0; nf < 4; nf++) {
                int br = wn * 32 + nf * 8 + (lane >> 2);
                int bc = kk + (lane & 3);
                unsigned bh0, bl0, bh1, bl1;
                tf32_split(sB[br * 20 + bc],     bh0, bl0);
                tf32_split(sB[br * 20 + bc + 4], bh1, bl1);
#pragma unroll
                for (int mf = 0; mf < 4; mf++) {
                    mma8(acc[mf][nf], al[mf][0], al[mf][1], al[mf][2], al[mf][3], bh0, bh1);
                    mma8(acc[mf][nf], ah[mf][0], ah[mf][1], ah[mf][2], ah[mf][3], bl0, bl1);
                    mma8(acc[mf][nf], ah[mf][0], ah[mf][1], ah[mf][2], ah[mf][3], bh0, bh1);
                }
            }
        }
        __syncthreads();
    }
#pragma unroll
    for (int mf = 0; mf < 4; mf++) {
        int r = row0 + wm * 64 + mf * 16 + (lane >> 2);
#pragma unroll
        for (int nf = 0; nf < 4; nf++) {
            int jl = wn * 32 + nf * 8 + (lane & 3) * 2;
            int jg = col0 + jl;
            float2 v0 = make_float2(acc[mf][nf][0] + sBias[jl], acc[mf][nf][1] + sBias[jl + 1]);
            float2 v1 = make_float2(acc[mf][nf][2] + sBias[jl], acc[mf][nf][3] + sBias[jl + 1]);
            *(float2*)&g_GBUF[(size_t)r * NGATE + jg] = v0;
            *(float2*)&g_GBUF[(size_t)(r + 8) * NGATE + jg] = v1;
        }
    }
}

// ---------------- persistent encoder layer ----------------
__global__ __launch_bounds__(256) void enc_layer_persistent(
    const float* __restrict__ whh, int layer)
{
    int tid = threadIdx.x, bid = blockIdx.x;
    int lane = tid & 31, w = tid >> 5;
    unsigned ep = epoch_init();
#pragma unroll
    for (int p = 0; p < 4; p++) {
        int idx = (bid * 4 + p) * 256 + tid;
        g_henc[0][idx] = 0.f;
    }
    sync_grid(ep); ep++;

    __shared__ float sA[128 * 36];
    __shared__ float sB[32 * 36];
    int dir = bid >> 6;
    int jblk = bid & 63;
    int p_base = bid * 32;
    float* Hout = layer ? g_ENC : g_H1;

    float creg[4] = {0.f, 0.f, 0.f, 0.f};
    int r0 = (w << 4) + (lane >> 2);
    int jj2 = (lane & 3) * 2;

    for (int t = 0; t < LSEQ; t++) {
        int time = dir ? (LSEQ - 1 - t) : t;
        const float* A = g_henc[t & 1] + dir * NB * HE;
        float* Awr = g_henc[(t + 1) & 1] + dir * NB * HE;
        float acc[4][4];
#pragma unroll
        for (int a = 0; a < 4; a++)
#pragma unroll
            for (int c = 0; c < 4; c++) acc[a][c] = 0.f;

        for (int k0 = 0; k0 < HE; k0 += 32) {
#pragma unroll
            for (int p = 0; p < 16; p++) {
                int idx = tid + p * 256;
                int r = idx >> 5, c = idx & 31;
                sA[r * 36 + c] = A[r * HE + k0 + c];
            }
#pragma unroll
            for (int p = 0; p < 4; p++) {
                int idx = tid + p * 256;
                int r = idx >> 5, c = idx & 31;
                int nat = dir * 2048 + (r >> 3) * 512 + jblk * 8 + (r & 7);
                sB[r * 36 + c] = whh[(size_t)nat * HE + k0 + c];
            }
            __syncthreads();
#pragma unroll
            for (int kk = 0; kk < 32; kk += 8) {
                int ac = kk + (lane & 3);
                unsigned ah[4], al[4];
                tf32_split(sA[r0 * 36 + ac],           ah[0], al[0]);
                tf32_split(sA[(r0 + 8) * 36 + ac],     ah[1], al[1]);
                tf32_split(sA[r0 * 36 + ac + 4],       ah[2], al[2]);
                tf32_split(sA[(r0 + 8) * 36 + ac + 4], ah[3], al[3]);
#pragma unroll
                for (int nf = 0; nf < 4; nf++) {
                    int br = nf * 8 + (lane >> 2);
                    int bc = kk + (lane & 3);
                    unsigned bh0, bl0, bh1, bl1;
                    tf32_split(sB[br * 36 + bc],     bh0, bl0);
                    tf32_split(sB[br * 36 + bc + 4], bh1, bl1);
                    mma8(acc[nf], al[0], al[1], al[2], al[3], bh0, bh1);
                    mma8(acc[nf], ah[0], ah[1], ah[2], ah[3], bl0, bl1);
                    mma8(acc[nf], ah[0], ah[1], ah[2], ah[3], bh0, bh1);
                }
            }
            __syncthreads();
        }
        // in-register pointwise; writes go to the OTHER h buffer (no cross-CTA race)
        {
            const float* Gin = g_GBUF + ((size_t)time * NB) * NGATE + p_base;
#pragma unroll
            for (int cell = 0; cell < 4; cell++) {
                int rr = r0 + (cell >> 1) * 8;
                int jloc = jj2 + (cell & 1);
                const float* Gr = Gin + (size_t)rr * NGATE;
                float gi = acc[0][cell] + Gr[jloc];
                float gf = acc[1][cell] + Gr[8 + jloc];
                float gg = acc[2][cell] + Gr[16 + jloc];
                float go = acc[3][cell] + Gr[24 + jloc];
                int j = jblk * 8 + jloc;
                float cc = creg[cell];
                cc = sigm(gf) * cc + sigm(gi) * tanhf(gg);
                float hh = sigm(go) * tanhf(cc);
                creg[cell] = cc;
                Awr[rr * HE + j] = hh;
                Hout[((size_t)time * NB + rr) * HD + dir * HE + j] = hh;
            }
        }
        sync_grid(ep); ep++;
    }
}

// ---------------- persistent decoder ----------------
__global__ __launch_bounds__(256) void dec_persistent(
    const float* __restrict__ whh, const float* __restrict__ bias,
    const float* __restrict__ wih,
    const float* __restrict__ out_w, const float* __restrict__ out_b,
    const int* __restrict__ tag_ids, float* __restrict__ prob_out)
{
    int tid = threadIdx.x, bid = blockIdx.x;
    int lane = tid & 31, w = tid >> 5;
    int r0 = (w << 4) + (lane >> 2);
    int jj2 = (lane & 3) * 2;
    int j0 = bid * 8;
    unsigned ep = epoch_init();

    // hsum[0] = h0(=0) + enc_0
#pragma unroll
    for (int p = 0; p < 4; p++) {
        int idx = (bid * 4 + p) * 256 + tid;
        g_hsum[0][idx] = g_ENC[idx];
    }
    if (bid == 0 && tid < NB) g_previdx[tid] = -1;
    if (bid == 0 && tid == 0) g_loss = 0.f;

    // register cell state: cell0 = enc[0][n][HE + (j & 511)]
    float creg[4];
#pragma unroll
    for (int cell = 0; cell < 4; cell++) {
        int rr = r0 + (cell >> 1) * 8;
        int j = j0 + jj2 + (cell & 1);
        creg[cell] = g_ENC[(size_t)rr * HD + HE + (j & (HE - 1))];
    }

    float biasReg[4][2];
#pragma unroll
    for (int g = 0; g < 4; g++) {
        biasReg[g][0] = bias[g * HD + j0 + jj2];
        biasReg[g][1] = bias[g * HD + j0 + jj2 + 1];
    }
    sync_grid(ep); ep++;

    __shared__ float sA[128 * 36];
    __shared__ float sB[32 * 36];
    __shared__ float sh[HD];
    __shared__ float red[256];
    __shared__ float logitsS[TT];
    __shared__ float sLogZ;
    __shared__ int sArg;

    for (int t = 0; t < LSEQ; t++) {
        const float* Ain = g_hsum[t & 1];
        float* Anext = g_hsum[(t + 1) & 1];
        float acc[4][4];
#pragma unroll
        for (int a = 0; a < 4; a++)
#pragma unroll
            for (int c = 0; c < 4; c++) acc[a][c] = 0.f;

        for (int k0 = 0; k0 < HD; k0 += 32) {
#pragma unroll
            for (int p = 0; p < 16; p++) {
                int idx = tid + p * 256;
                int r = idx >> 5, c = idx & 31;
                sA[r * 36 + c] = Ain[(size_t)r * HD + k0 + c];
            }
#pragma unroll
            for (int p = 0; p < 4; p++) {
                int idx = tid + p * 256;
                int r = idx >> 5, c = idx & 31;
                int nat = (r >> 3) * HD + j0 + (r & 7);
                sB[r * 36 + c] = whh[(size_t)nat * HD + k0 + c];
            }
            __syncthreads();
#pragma unroll
            for (int kk = 0; kk < 32; kk += 8) {
                int ac = kk + (lane & 3);
                unsigned ah[4], al[4];
                tf32_split(sA[r0 * 36 + ac],           ah[0], al[0]);
                tf32_split(sA[(r0 + 8) * 36 + ac],     ah[1], al[1]);
                tf32_split(sA[r0 * 36 + ac + 4],       ah[2], al[2]);
                tf32_split(sA[(r0 + 8) * 36 + ac + 4], ah[3], al[3]);
#pragma unroll
                for (int nf = 0; nf < 4; nf++) {
                    int br = nf * 8 + (lane >> 2);
                    int bc = kk + (lane & 3);
                    unsigned bh0, bl0, bh1, bl1;
                    tf32_split(sB[br * 36 + bc],     bh0, bl0);
                    tf32_split(sB[br * 36 + bc + 4], bh1, bl1);
                    mma8(acc[nf], al[0], al[1], al[2], al[3], bh0, bh1);
                    mma8(acc[nf], ah[0], ah[1], ah[2], ah[3], bl0, bl1);
                    mma8(acc[nf], ah[0], ah[1], ah[2], ah[3], bh0, bh1);
                }
            }
            __syncthreads();
        }
        // pointwise: write raw h (for logits) + h+enc_{t+1} (next GEMM A) into ping buffer
        {
            int pv0 = g_previdx[r0];
            int pv1 = g_previdx[r0 + 8];
#pragma unroll
            for (int cell = 0; cell < 4; cell++) {
                int rr = r0 + (cell >> 1) * 8;
                int pv = (cell >> 1) ? pv1 : pv0;
                int s = cell & 1;
                int jloc = jj2 + s;
                int j = j0 + jloc;
                float gi = acc[0][cell] + biasReg[0][s];
                float gf = acc[1][cell] + biasReg[1][s];
                float gg = acc[2][cell] + biasReg[2][s];
                float go = acc[3][cell] + biasReg[3][s];
                if (pv >= 0) {
                    gi += wih[(0 * HD + j) * TT + pv];
                    gf += wih[(1 * HD + j) * TT + pv];
                    gg += wih[(2 * HD + j) * TT + pv];
                    go += wih[(3 * HD + j) * TT + pv];
                }
                float cc = creg[cell];
                cc = sigm(gf) * cc + sigm(gi) * tanhf(gg);
                float hh = sigm(go) * tanhf(cc);
                creg[cell] = cc;
                g_hraw[rr * HD + j] = hh;
                if (t + 1 < LSEQ)
                    Anext[(size_t)rr * HD + j] = hh + g_ENC[((size_t)(t + 1) * NB + rr) * HD + j];
            }
        }
        sync_grid(ep); ep++;
        // logits + softmax + argmax + loss: CTA bid handles batch row bid
        {
            int n = bid;
#pragma unroll
            for (int p = 0; p < 4; p++) {
                int j = tid + p * 256;
                sh[j] = g_hraw[n * HD + j];
            }
            __syncthreads();
            {
                int lj = tid & (TT - 1), half = tid >> 7;
                const float* wr = out_w + (size_t)lj * HD + half * 512;
                const float* hr = sh + half * 512;
                float s = 0.f;
#pragma unroll 8
                for (int k = 0; k < 512; k++) s += hr[k] * wr[k];
                red[tid] = s;
            }
            __syncthreads();
            if (tid < TT) logitsS[tid] = red[tid] + red[tid + TT] + out_b[tid];
            __syncthreads();
            if (tid < 32) {
                float bv = -1e30f; int bi = 0;
#pragma unroll
                for (int p = 0; p < 4; p++) {
                    int k = tid + p * 32;
                    float v = logitsS[k];
                    if (v > bv) { bv = v; bi = k; }
                }
#pragma unroll
                for (int off = 16; off; off >>= 1) {
                    float ov = __shfl_down_sync(0xffffffffu, bv, off);
                    int   oi = __shfl_down_sync(0xffffffffu, bi, off);
                    if (ov > bv || (ov == bv && oi < bi)) { bv = ov; bi = oi; }
                }
                bv = __shfl_sync(0xffffffffu, bv, 0);
                bi = __shfl_sync(0xffffffffu, bi, 0);
                float s = 0.f;
#pragma unroll
                for (int p = 0; p < 4; p++) s += expf(logitsS[tid + p * 32] - bv);
#pragma unroll
                for (int off = 16; off; off >>= 1) s += __shfl_down_sync(0xffffffffu, s, off);
                if (tid == 0) { sLogZ = bv + logf(s); sArg = bi; }
            }
            __syncthreads();
            if (tid < TT)
                prob_out[(size_t)n * (LSEQ * TT) + t * TT + tid] = expf(logitsS[tid] - sLogZ);
            if (tid == 0) {
                g_previdx[n] = sArg;
                int tag = tag_ids[n * LSEQ + t];
                atomicAdd(&g_loss, -(logitsS[tag] - sLogZ) * (1.0f / NB));
            }
        }
        sync_grid(ep); ep++;
    }
    if (bid == 0 && tid == 0) prob_out[(size_t)NB * LSEQ * TT] = g_loss;
}

// ---------------- launch: 5 graph nodes ----------------
extern "C" void kernel_launch(void* const* d_in, const int* in_sizes, int n_in,
                              void* d_out, int out_size)
{
    const int*   input_ids = (const int*)d_in[0];
    const int*   tag_ids   = (const int*)d_in[1];
    const float* embed     = (const float*)d_in[2];
    const float* e0_wih    = (const float*)d_in[3];
    const float* e0_whh    = (const float*)d_in[4];
    const float* e0_b      = (const float*)d_in[5];
    const float* e1_wih    = (const float*)d_in[6];
    const float* e1_whh    = (const float*)d_in[7];
    const float* e1_b      = (const float*)d_in[8];
    const float* dec_wih   = (const float*)d_in[9];
    const float* dec_whh   = (const float*)d_in[10];
    const float* dec_b     = (const float*)d_in[11];
    const float* out_w     = (const float*)d_in[12];
    const float* out_b     = (const float*)d_in[13];
    float* out = (float*)d_out;
    (void)in_sizes; (void)n_in; (void)out_size;

    dim3 ggrid(NGATE / 128, (LSEQ * NB) / 128);   // 32 x 160

    inproj_gemm<1, EMB><<<ggrid, 256>>>(e0_wih, e0_b, embed, input_ids);
    enc_layer_persistent<<<GRID, 256>>>(e0_whh, 0);
    inproj_gemm<0, HD><<<ggrid, 256>>>(e1_wih, e1_b, embed, input_ids);
    enc_layer_persistent<<<GRID, 256>>>(e1_whh, 1);
    dec_persistent<<<GRID, 256>>>(dec_whh, dec_b, dec_wih, out_w, out_b, tag_ids, out);
}

// round 9
// speedup vs baseline: 1.0442x; 1.0442x over previous
#include <cuda_runtime.h>
#include <cmath>

#define NB   128
#define LSEQ 160
#define EMB  512
#define HE   512
#define HD   1024
#define TT   128
#define NGATE 4096
#define GRID 128

// ---------------- scratch ----------------
static __device__ float g_GBUF[(size_t)LSEQ * NB * NGATE];   // input-proj gates (PERMUTED cols)
static __device__ float g_H1 [(size_t)LSEQ * NB * (2 * HE)];
static __device__ float g_ENC[(size_t)LSEQ * NB * (2 * HE)];
static __device__ float g_henc[2][2 * NB * HE];              // encoder h, ping-pong
static __device__ float g_hraw[NB * HD];                     // decoder raw h_t (logits input)
static __device__ float g_hsum[2][NB * HD];                  // decoder h_{t-1}+enc_t, ping-pong
static __device__ __align__(128) int   g_previdx[NB];
static __device__ __align__(128) float g_loss;

// ---- distributed grid barrier state (each element on its own 128B line) ----
static __device__ __align__(128) unsigned g_cnt[8 * 32];     // 8 arrival counters
static __device__ __align__(128) unsigned g_lvl2[32];        // level-2 counter
static __device__ __align__(128) unsigned g_phaseA[16 * 32]; // 16 broadcast phase copies

__device__ __forceinline__ float sigm(float x) { return 1.0f / (1.0f + expf(-x)); }

// tf32 helpers: exact-ish fp32 GEMM via 3-term split
__device__ __forceinline__ unsigned tf32_of(float x) {
    unsigned u; asm("cvt.rna.tf32.f32 %0, %1;" : "=r"(u) : "f"(x)); return u;
}
__device__ __forceinline__ void tf32_split(float x, unsigned& hi, unsigned& lo) {
    hi = tf32_of(x);
    lo = tf32_of(x - __uint_as_float(hi));
}
__device__ __forceinline__ void mma8(float* c, unsigned a0, unsigned a1, unsigned a2, unsigned a3,
                                     unsigned b0, unsigned b1) {
    asm volatile("mma.sync.aligned.m16n8k8.row.col.f32.tf32.tf32.f32 "
                 "{%0,%1,%2,%3}, {%4,%5,%6,%7}, {%8,%9}, {%0,%1,%2,%3};"
                 : "+f"(c[0]), "+f"(c[1]), "+f"(c[2]), "+f"(c[3])
                 : "r"(a0), "r"(a1), "r"(a2), "r"(a3), "r"(b0), "r"(b1));
}

// Tree grid barrier. epoch values are monotonic (persist across kernels/replays).
// Arrivals: 8 padded counters (16 CTAs each). CTA0 threads 0-7 detect level-1,
// funnel into one level-2 counter; thread 0 broadcasts the new phase to 16
// padded read-only flag lines (8 polling CTAs per line).
__device__ __forceinline__ void sync_grid(unsigned ep)
{
    __syncthreads();
    int tid = threadIdx.x, bid = blockIdx.x;
    if (bid == 0) {
        if (tid == 0)
            asm volatile("red.release.gpu.add.u32 [%0], 1;" :: "l"(&g_cnt[0]) : "memory");
        if (tid < 8) {
            unsigned tgt = ep * 16u, v;
            do {
                asm volatile("ld.acquire.gpu.u32 %0, [%1];"
                             : "=r"(v) : "l"(&g_cnt[tid * 32]) : "memory");
            } while ((int)(v - tgt) < 0);
            asm volatile("red.release.gpu.add.u32 [%0], 1;" :: "l"(&g_lvl2[0]) : "memory");
        }
        if (tid == 0) {
            unsigned tgt2 = ep * 8u, v;
            do {
                asm volatile("ld.acquire.gpu.u32 %0, [%1];"
                             : "=r"(v) : "l"(&g_lvl2[0]) : "memory");
            } while ((int)(v - tgt2) < 0);
#pragma unroll
            for (int i = 0; i < 16; i++)
                asm volatile("st.release.gpu.u32 [%0], %1;"
                             :: "l"(&g_phaseA[i * 32]), "r"(ep) : "memory");
        }
    } else if (tid == 0) {
        asm volatile("red.release.gpu.add.u32 [%0], 1;"
                     :: "l"(&g_cnt[(bid & 7) * 32]) : "memory");
        const unsigned* flag = &g_phaseA[((bid >> 3) & 15) * 32];
        unsigned v, slp = 128;
        int miss = 0;
        for (;;) {
            asm volatile("ld.acquire.gpu.u32 %0, [%1];" : "=r"(v) : "l"(flag) : "memory");
            if ((int)(v - ep) >= 0) break;
            if (++miss > 4) { __nanosleep(slp); if (slp < 2048) slp <<= 1; }
        }
    }
    __syncthreads();
}

__device__ __forceinline__ unsigned epoch_init()
{
    unsigned p;
    asm volatile("ld.relaxed.gpu.u32 %0, [%1];" : "=r"(p) : "l"(&g_phaseA[0]) : "memory");
    return p + 1;
}

// permuted-col map (encoder, per 2048-col dir block):
// p = jblk*32 + gate*8 + jj  <->  natural = gate*512 + jblk*8 + jj

// ---------------- input-projection GEMM (tf32x3 mma), writes PERMUTED gate cols ----------------
template <int GATHER, int K>
__global__ __launch_bounds__(256) void inproj_gemm(
    const float* __restrict__ W, const float* __restrict__ bias,
    const float* __restrict__ embed, const int* __restrict__ ids)
{
    __shared__ float sA[128 * 20];
    __shared__ float sB[128 * 20];
    __shared__ int   rowoff[128];
    __shared__ int   natrow[128];
    __shared__ float sBias[128];
    int tid = threadIdx.x;
    int row0 = blockIdx.y * 128;
    int col0 = blockIdx.x * 128;
    if (tid < 128) {
        int p = col0 + tid;
        int dir = p >> 11;
        int q = p & 2047;
        int nat = dir * 2048 + ((q >> 3) & 3) * 512 + (q >> 5) * 8 + (q & 7);
        natrow[tid] = nat;
        sBias[tid] = bias[nat];
        if (GATHER) {
            int m = row0 + tid;
            rowoff[tid] = ids[(m & (NB - 1)) * LSEQ + (m >> 7)] * EMB;
        }
    }
    __syncthreads();
    int lane = tid & 31, w = tid >> 5;
    int wm = w >> 2, wn = w & 3;
    float acc[4][4][4];
#pragma unroll
    for (int a = 0; a < 4; a++)
#pragma unroll
        for (int b = 0; b < 4; b++)
#pragma unroll
            for (int c = 0; c < 4; c++) acc[a][b][c] = 0.f;

    for (int k0 = 0; k0 < K; k0 += 16) {
#pragma unroll
        for (int p = 0; p < 8; p++) {
            int idx = tid + p * 256;
            int r = idx >> 4, c = idx & 15;
            float v;
            if (GATHER) v = embed[rowoff[r] + k0 + c];
            else        v = g_H1[(size_t)(row0 + r) * K + k0 + c];
            sA[r * 20 + c] = v;
            sB[r * 20 + c] = W[(size_t)natrow[r] * K + k0 + c];
        }
        __syncthreads();
#pragma unroll
        for (int kk = 0; kk < 16; kk += 8) {
            unsigned ah[4][4], al[4][4];
#pragma unroll
            for (int mf = 0; mf < 4; mf++) {
                int ar = wm * 64 + mf * 16 + (lane >> 2);
                int ac = kk + (lane & 3);
                tf32_split(sA[ar * 20 + ac],           ah[mf][0], al[mf][0]);
                tf32_split(sA[(ar + 8) * 20 + ac],     ah[mf][1], al[mf][1]);
                tf32_split(sA[ar * 20 + ac + 4],       ah[mf][2], al[mf][2]);
                tf32_split(sA[(ar + 8) * 20 + ac + 4], ah[mf][3], al[mf][3]);
            }
#pragma unroll
            for (int nf = 0; nf < 4; nf++) {
                int br = wn * 32 + nf * 8 + (lane >> 2);
                int bc = kk + (lane & 3);
                unsigned bh0, bl0, bh1, bl1;
                tf32_split(sB[br * 20 + bc],     bh0, bl0);
                tf32_split(sB[br * 20 + bc + 4], bh1, bl1);
#pragma unroll
                for (int mf = 0; mf < 4; mf++) {
                    mma8(acc[mf][nf], al[mf][0], al[mf][1], al[mf][2], al[mf][3], bh0, bh1);
                    mma8(acc[mf][nf], ah[mf][0], ah[mf][1], ah[mf][2], ah[mf][3], bl0, bl1);
                    mma8(acc[mf][nf], ah[mf][0], ah[mf][1], ah[mf][2], ah[mf][3], bh0, bh1);
                }
            }
        }
        __syncthreads();
    }
#pragma unroll
    for (int mf = 0; mf < 4; mf++) {
        int r = row0 + wm * 64 + mf * 16 + (lane >> 2);
#pragma unroll
        for (int nf = 0; nf < 4; nf++) {
            int jl = wn * 32 + nf * 8 + (lane & 3) * 2;
            int jg = col0 + jl;
            float2 v0 = make_float2(acc[mf][nf][0] + sBias[jl], acc[mf][nf][1] + sBias[jl + 1]);
            float2 v1 = make_float2(acc[mf][nf][2] + sBias[jl], acc[mf][nf][3] + sBias[jl + 1]);
            *(float2*)&g_GBUF[(size_t)r * NGATE + jg] = v0;
            *(float2*)&g_GBUF[(size_t)(r + 8) * NGATE + jg] = v1;
        }
    }
}

// ---------------- persistent encoder layer ----------------
__global__ __launch_bounds__(256) void enc_layer_persistent(
    const float* __restrict__ whh, int layer)
{
    int tid = threadIdx.x, bid = blockIdx.x;
    int lane = tid & 31, w = tid >> 5;
    unsigned ep = epoch_init();
#pragma unroll
    for (int p = 0; p < 4; p++) {
        int idx = (bid * 4 + p) * 256 + tid;
        g_henc[0][idx] = 0.f;
    }
    sync_grid(ep); ep++;

    __shared__ float sA[128 * 36];
    __shared__ float sB[32 * 36];
    int dir = bid >> 6;
    int jblk = bid & 63;
    int p_base = bid * 32;
    float* Hout = layer ? g_ENC : g_H1;

    float creg[4] = {0.f, 0.f, 0.f, 0.f};
    int r0 = (w << 4) + (lane >> 2);
    int jj2 = (lane & 3) * 2;

    for (int t = 0; t < LSEQ; t++) {
        int time = dir ? (LSEQ - 1 - t) : t;
        const float* A = g_henc[t & 1] + dir * NB * HE;
        float* Awr = g_henc[(t + 1) & 1] + dir * NB * HE;
        float acc[4][4];
#pragma unroll
        for (int a = 0; a < 4; a++)
#pragma unroll
            for (int c = 0; c < 4; c++) acc[a][c] = 0.f;

        for (int k0 = 0; k0 < HE; k0 += 32) {
#pragma unroll
            for (int p = 0; p < 16; p++) {
                int idx = tid + p * 256;
                int r = idx >> 5, c = idx & 31;
                sA[r * 36 + c] = A[r * HE + k0 + c];
            }
#pragma unroll
            for (int p = 0; p < 4; p++) {
                int idx = tid + p * 256;
                int r = idx >> 5, c = idx & 31;
                int nat = dir * 2048 + (r >> 3) * 512 + jblk * 8 + (r & 7);
                sB[r * 36 + c] = whh[(size_t)nat * HE + k0 + c];
            }
            __syncthreads();
#pragma unroll
            for (int kk = 0; kk < 32; kk += 8) {
                int ac = kk + (lane & 3);
                unsigned ah[4], al[4];
                tf32_split(sA[r0 * 36 + ac],           ah[0], al[0]);
                tf32_split(sA[(r0 + 8) * 36 + ac],     ah[1], al[1]);
                tf32_split(sA[r0 * 36 + ac + 4],       ah[2], al[2]);
                tf32_split(sA[(r0 + 8) * 36 + ac + 4], ah[3], al[3]);
#pragma unroll
                for (int nf = 0; nf < 4; nf++) {
                    int br = nf * 8 + (lane >> 2);
                    int bc = kk + (lane & 3);
                    unsigned bh0, bl0, bh1, bl1;
                    tf32_split(sB[br * 36 + bc],     bh0, bl0);
                    tf32_split(sB[br * 36 + bc + 4], bh1, bl1);
                    mma8(acc[nf], al[0], al[1], al[2], al[3], bh0, bh1);
                    mma8(acc[nf], ah[0], ah[1], ah[2], ah[3], bl0, bl1);
                    mma8(acc[nf], ah[0], ah[1], ah[2], ah[3], bh0, bh1);
                }
            }
            __syncthreads();
        }
        // in-register pointwise; writes go to the OTHER h buffer (no cross-CTA race)
        {
            const float* Gin = g_GBUF + ((size_t)time * NB) * NGATE + p_base;
#pragma unroll
            for (int cell = 0; cell < 4; cell++) {
                int rr = r0 + (cell >> 1) * 8;
                int jloc = jj2 + (cell & 1);
                const float* Gr = Gin + (size_t)rr * NGATE;
                float gi = acc[0][cell] + Gr[jloc];
                float gf = acc[1][cell] + Gr[8 + jloc];
                float gg = acc[2][cell] + Gr[16 + jloc];
                float go = acc[3][cell] + Gr[24 + jloc];
                int j = jblk * 8 + jloc;
                float cc = creg[cell];
                cc = sigm(gf) * cc + sigm(gi) * tanhf(gg);
                float hh = sigm(go) * tanhf(cc);
                creg[cell] = cc;
                Awr[rr * HE + j] = hh;
                Hout[((size_t)time * NB + rr) * HD + dir * HE + j] = hh;
            }
        }
        sync_grid(ep); ep++;
    }
}

// ---------------- persistent decoder ----------------
__global__ __launch_bounds__(256) void dec_persistent(
    const float* __restrict__ whh, const float* __restrict__ bias,
    const float* __restrict__ wih,
    const float* __restrict__ out_w, const float* __restrict__ out_b,
    const int* __restrict__ tag_ids, float* __restrict__ prob_out)
{
    int tid = threadIdx.x, bid = blockIdx.x;
    int lane = tid & 31, w = tid >> 5;
    int r0 = (w << 4) + (lane >> 2);
    int jj2 = (lane & 3) * 2;
    int j0 = bid * 8;
    unsigned ep = epoch_init();

    // hsum[0] = h0(=0) + enc_0
#pragma unroll
    for (int p = 0; p < 4; p++) {
        int idx = (bid * 4 + p) * 256 + tid;
        g_hsum[0][idx] = g_ENC[idx];
    }
    if (bid == 0 && tid < NB) g_previdx[tid] = -1;
    if (bid == 0 && tid == 0) g_loss = 0.f;

    // register cell state: cell0 = enc[0][n][HE + (j & 511)]
    float creg[4];
#pragma unroll
    for (int cell = 0; cell < 4; cell++) {
        int rr = r0 + (cell >> 1) * 8;
        int j = j0 + jj2 + (cell & 1);
        creg[cell] = g_ENC[(size_t)rr * HD + HE + (j & (HE - 1))];
    }

    float biasReg[4][2];
#pragma unroll
    for (int g = 0; g < 4; g++) {
        biasReg[g][0] = bias[g * HD + j0 + jj2];
        biasReg[g][1] = bias[g * HD + j0 + jj2 + 1];
    }
    sync_grid(ep); ep++;

    __shared__ float sA[128 * 36];
    __shared__ float sB[32 * 36];
    __shared__ float sh[HD];
    __shared__ float red[256];
    __shared__ float logitsS[TT];
    __shared__ float sLogZ;
    __shared__ int sArg;

    for (int t = 0; t < LSEQ; t++) {
        const float* Ain = g_hsum[t & 1];
        float* Anext = g_hsum[(t + 1) & 1];
        float acc[4][4];
#pragma unroll
        for (int a = 0; a < 4; a++)
#pragma unroll
            for (int c = 0; c < 4; c++) acc[a][c] = 0.f;

        for (int k0 = 0; k0 < HD; k0 += 32) {
#pragma unroll
            for (int p = 0; p < 16; p++) {
                int idx = tid + p * 256;
                int r = idx >> 5, c = idx & 31;
                sA[r * 36 + c] = Ain[(size_t)r * HD + k0 + c];
            }
#pragma unroll
            for (int p = 0; p < 4; p++) {
                int idx = tid + p * 256;
                int r = idx >> 5, c = idx & 31;
                int nat = (r >> 3) * HD + j0 + (r & 7);
                sB[r * 36 + c] = whh[(size_t)nat * HD + k0 + c];
            }
            __syncthreads();
#pragma unroll
            for (int kk = 0; kk < 32; kk += 8) {
                int ac = kk + (lane & 3);
                unsigned ah[4], al[4];
                tf32_split(sA[r0 * 36 + ac],           ah[0], al[0]);
                tf32_split(sA[(r0 + 8) * 36 + ac],     ah[1], al[1]);
                tf32_split(sA[r0 * 36 + ac + 4],       ah[2], al[2]);
                tf32_split(sA[(r0 + 8) * 36 + ac + 4], ah[3], al[3]);
#pragma unroll
                for (int nf = 0; nf < 4; nf++) {
                    int br = nf * 8 + (lane >> 2);
                    int bc = kk + (lane & 3);
                    unsigned bh0, bl0, bh1, bl1;
                    tf32_split(sB[br * 36 + bc],     bh0, bl0);
                    tf32_split(sB[br * 36 + bc + 4], bh1, bl1);
                    mma8(acc[nf], al[0], al[1], al[2], al[3], bh0, bh1);
                    mma8(acc[nf], ah[0], ah[1], ah[2], ah[3], bl0, bl1);
                    mma8(acc[nf], ah[0], ah[1], ah[2], ah[3], bh0, bh1);
                }
            }
            __syncthreads();
        }
        // pointwise: write raw h (for logits) + h+enc_{t+1} (next GEMM A) into ping buffer
        {
            int pv0 = g_previdx[r0];
            int pv1 = g_previdx[r0 + 8];
#pragma unroll
            for (int cell = 0; cell < 4; cell++) {
                int rr = r0 + (cell >> 1) * 8;
                int pv = (cell >> 1) ? pv1 : pv0;
                int s = cell & 1;
                int jloc = jj2 + s;
                int j = j0 + jloc;
                float gi = acc[0][cell] + biasReg[0][s];
                float gf = acc[1][cell] + biasReg[1][s];
                float gg = acc[2][cell] + biasReg[2][s];
                float go = acc[3][cell] + biasReg[3][s];
                if (pv >= 0) {
                    gi += wih[(0 * HD + j) * TT + pv];
                    gf += wih[(1 * HD + j) * TT + pv];
                    gg += wih[(2 * HD + j) * TT + pv];
                    go += wih[(3 * HD + j) * TT + pv];
                }
                float cc = creg[cell];
                cc = sigm(gf) * cc + sigm(gi) * tanhf(gg);
                float hh = sigm(go) * tanhf(cc);
                creg[cell] = cc;
                g_hraw[rr * HD + j] = hh;
                if (t + 1 < LSEQ)
                    Anext[(size_t)rr * HD + j] = hh + g_ENC[((size_t)(t + 1) * NB + rr) * HD + j];
            }
        }
        sync_grid(ep); ep++;
        // logits + softmax + argmax + loss: CTA bid handles batch row bid
        {
            int n = bid;
#pragma unroll
            for (int p = 0; p < 4; p++) {
                int j = tid + p * 256;
                sh[j] = g_hraw[n * HD + j];
            }
            __syncthreads();
            {
                int lj = tid & (TT - 1), half = tid >> 7;
                const float* wr = out_w + (size_t)lj * HD + half * 512;
                const float* hr = sh + half * 512;
                float s = 0.f;
#pragma unroll 8
                for (int k = 0; k < 512; k++) s += hr[k] * wr[k];
                red[tid] = s;
            }
            __syncthreads();
            if (tid < TT) logitsS[tid] = red[tid] + red[tid + TT] + out_b[tid];
            __syncthreads();
            if (tid < 32) {
                float bv = -1e30f; int bi = 0;
#pragma unroll
                for (int p = 0; p < 4; p++) {
                    int k = tid + p * 32;
                    float v = logitsS[k];
                    if (v > bv) { bv = v; bi = k; }
                }
#pragma unroll
                for (int off = 16; off; off >>= 1) {
                    float ov = __shfl_down_sync(0xffffffffu, bv, off);
                    int   oi = __shfl_down_sync(0xffffffffu, bi, off);
                    if (ov > bv || (ov == bv && oi < bi)) { bv = ov; bi = oi; }
                }
                bv = __shfl_sync(0xffffffffu, bv, 0);
                bi = __shfl_sync(0xffffffffu, bi, 0);
                float s = 0.f;
#pragma unroll
                for (int p = 0; p < 4; p++) s += expf(logitsS[tid + p * 32] - bv);
#pragma unroll
                for (int off = 16; off; off >>= 1) s += __shfl_down_sync(0xffffffffu, s, off);
                if (tid == 0) { sLogZ = bv + logf(s); sArg = bi; }
            }
            __syncthreads();
            if (tid < TT)
                prob_out[(size_t)n * (LSEQ * TT) + t * TT + tid] = expf(logitsS[tid] - sLogZ);
            if (tid == 0) {
                g_previdx[n] = sArg;
                int tag = tag_ids[n * LSEQ + t];
                atomicAdd(&g_loss, -(logitsS[tag] - sLogZ) * (1.0f / NB));
            }
        }
        sync_grid(ep); ep++;
    }
    if (bid == 0 && tid == 0) prob_out[(size_t)NB * LSEQ * TT] = g_loss;
}

// ---------------- launch: 5 graph nodes ----------------
extern "C" void kernel_launch(void* const* d_in, const int* in_sizes, int n_in,
                              void* d_out, int out_size)
{
    const int*   input_ids = (const int*)d_in[0];
    const int*   tag_ids   = (const int*)d_in[1];
    const float* embed     = (const float*)d_in[2];
    const float* e0_wih    = (const float*)d_in[3];
    const float* e0_whh    = (const float*)d_in[4];
    const float* e0_b      = (const float*)d_in[5];
    const float* e1_wih    = (const float*)d_in[6];
    const float* e1_whh    = (const float*)d_in[7];
    const float* e1_b      = (const float*)d_in[8];
    const float* dec_wih   = (const float*)d_in[9];
    const float* dec_whh   = (const float*)d_in[10];
    const float* dec_b     = (const float*)d_in[11];
    const float* out_w     = (const float*)d_in[12];
    const float* out_b     = (const float*)d_in[13];
    float* out = (float*)d_out;
    (void)in_sizes; (void)n_in; (void)out_size;

    dim3 ggrid(NGATE / 128, (LSEQ * NB) / 128);   // 32 x 160

    inproj_gemm<1, EMB><<<ggrid, 256>>>(e0_wih, e0_b, embed, input_ids);
    enc_layer_persistent<<<GRID, 256>>>(e0_whh, 0);
    inproj_gemm<0, HD><<<ggrid, 256>>>(e1_wih, e1_b, embed, input_ids);
    enc_layer_persistent<<<GRID, 256>>>(e1_whh, 1);
    dec_persistent<<<GRID, 256>>>(dec_whh, dec_b, dec_wih, out_w, out_b, tag_ids, out);
}

// round 11
// speedup vs baseline: 1.1854x; 1.1351x over previous
#include <cuda_runtime.h>
#include <cmath>

#define NB   128
#define LSEQ 160
#define EMB  512
#define HE   512
#define HD   1024
#define TT   128
#define NGATE 4096
#define GRID 128

// ---------------- scratch ----------------
static __device__ float g_GBUF[(size_t)LSEQ * NB * NGATE];   // inproj gates, permuted col = jblk*32 + jj*4 + gate
static __device__ float g_H1 [(size_t)LSEQ * NB * (2 * HE)];
static __device__ float g_ENC[(size_t)LSEQ * NB * (2 * HE)];
static __device__ float g_henc[2][2 * NB * HE];
static __device__ float g_hraw[NB * HD];
static __device__ float g_hsum[2][NB * HD];
static __device__ __align__(128) int   g_previdx[NB];
static __device__ __align__(128) float g_loss;
static __device__ __align__(128) unsigned g_arrive;
// pre-split weight planes (natural layout)
static __device__ float g_e0H[2097152], g_e0L[2097152];
static __device__ float g_e1H[2097152], g_e1L[2097152];
static __device__ float g_dH[4194304],  g_dL[4194304];

__device__ __forceinline__ float sigm(float x) { return 1.0f / (1.0f + expf(-x)); }
__device__ __forceinline__ unsigned tf32_of(float x) {
    unsigned u; asm("cvt.rna.tf32.f32 %0, %1;" : "=r"(u) : "f"(x)); return u;
}
__device__ __forceinline__ void tf32_split(float x, unsigned& hi, unsigned& lo) {
    hi = tf32_of(x); lo = tf32_of(x - __uint_as_float(hi));
}
__device__ __forceinline__ void mma8(float* c, unsigned a0, unsigned a1, unsigned a2, unsigned a3,
                                     unsigned b0, unsigned b1) {
    asm volatile("mma.sync.aligned.m16n8k8.row.col.f32.tf32.tf32.f32 "
                 "{%0,%1,%2,%3}, {%4,%5,%6,%7}, {%8,%9}, {%0,%1,%2,%3};"
                 : "+f"(c[0]), "+f"(c[1]), "+f"(c[2]), "+f"(c[3])
                 : "r"(a0), "r"(a1), "r"(a2), "r"(a3), "r"(b0), "r"(b1));
}

// simple phase-bit grid barrier (R7-proven)
__device__ __forceinline__ void sync_grid()
{
    __syncthreads();
    if (threadIdx.x == 0) {
        unsigned add = (blockIdx.x == 0) ? (0x80000000u - (GRID - 1u)) : 1u;
        unsigned old, cur;
        asm volatile("atom.add.release.gpu.u32 %0, [%1], %2;"
                     : "=r"(old) : "l"(&g_arrive), "r"(add) : "memory");
        int spins = 0;
        for (;;) {
            asm volatile("ld.acquire.gpu.u32 %0, [%1];"
                         : "=r"(cur) : "l"(&g_arrive) : "memory");
            if ((old ^ cur) & 0x80000000u) break;
            if (++spins > 16) __nanosleep(64);
        }
    }
    __syncthreads();
}

// ---------------- weight pre-split ----------------
__global__ void split_sel(const float* __restrict__ src, int which, int n)
{
    float *h, *l;
    if (which == 0)      { h = g_e0H; l = g_e0L; }
    else if (which == 1) { h = g_e1H; l = g_e1L; }
    else                 { h = g_dH;  l = g_dL;  }
    int i = blockIdx.x * blockDim.x + threadIdx.x;
    if (i < n) {
        float x = src[i];
        unsigned hi = tf32_of(x);
        h[i] = __uint_as_float(hi);
        l[i] = __uint_as_float(tf32_of(x - __uint_as_float(hi)));
    }
}

// ---------------- input-projection GEMM ----------------
template <int GATHER, int K>
__global__ __launch_bounds__(256) void inproj_gemm(
    const float* __restrict__ W, const float* __restrict__ bias,
    const float* __restrict__ embed, const int* __restrict__ ids)
{
    __shared__ float sA[128 * 20];
    __shared__ float sB[128 * 20];
    __shared__ int   rowoff[128];
    __shared__ int   natrow[128];
    __shared__ float sBias[128];
    int tid = threadIdx.x;
    int row0 = blockIdx.y * 128;
    int col0 = blockIdx.x * 128;
    if (tid < 128) {
        int p = col0 + tid;
        int dir = p >> 11;
        int q2 = p & 2047;
        int c = q2 & 31;
        int nat = dir * 2048 + (c & 3) * 512 + (q2 >> 5) * 8 + (c >> 2);
        natrow[tid] = nat;
        sBias[tid] = bias[nat];
        if (GATHER) {
            int m = row0 + tid;
            rowoff[tid] = ids[(m & (NB - 1)) * LSEQ + (m >> 7)] * EMB;
        }
    }
    __syncthreads();
    int lane = tid & 31, w = tid >> 5;
    int wm = w >> 2, wn = w & 3;
    float acc[4][4][4];
#pragma unroll
    for (int a = 0; a < 4; a++)
#pragma unroll
        for (int b = 0; b < 4; b++)
#pragma unroll
            for (int c = 0; c < 4; c++) acc[a][b][c] = 0.f;

    for (int k0 = 0; k0 < K; k0 += 16) {
#pragma unroll
        for (int p = 0; p < 8; p++) {
            int idx = tid + p * 256;
            int r = idx >> 4, c = idx & 15;
            float v;
            if (GATHER) v = embed[rowoff[r] + k0 + c];
            else        v = g_H1[(size_t)(row0 + r) * K + k0 + c];
            sA[r * 20 + c] = v;
            sB[r * 20 + c] = W[(size_t)natrow[r] * K + k0 + c];
        }
        __syncthreads();
#pragma unroll
        for (int kk = 0; kk < 16; kk += 8) {
            unsigned ah[4][4], al[4][4];
#pragma unroll
            for (int mf = 0; mf < 4; mf++) {
                int ar = wm * 64 + mf * 16 + (lane >> 2);
                int ac = kk + (lane & 3);
                tf32_split(sA[ar * 20 + ac],           ah[mf][0], al[mf][0]);
                tf32_split(sA[(ar + 8) * 20 + ac],     ah[mf][1], al[mf][1]);
                tf32_split(sA[ar * 20 + ac + 4],       ah[mf][2], al[mf][2]);
                tf32_split(sA[(ar + 8) * 20 + ac + 4], ah[mf][3], al[mf][3]);
            }
#pragma unroll
            for (int nf = 0; nf < 4; nf++) {
                int br = wn * 32 + nf * 8 + (lane >> 2);
                int bc = kk + (lane & 3);
                unsigned bh0, bl0, bh1, bl1;
                tf32_split(sB[br * 20 + bc],     bh0, bl0);
                tf32_split(sB[br * 20 + bc + 4], bh1, bl1);
#pragma unroll
                for (int mf = 0; mf < 4; mf++) {
                    mma8(acc[mf][nf], al[mf][0], al[mf][1], al[mf][2], al[mf][3], bh0, bh1);
                    mma8(acc[mf][nf], ah[mf][0], ah[mf][1], ah[mf][2], ah[mf][3], bl0, bl1);
                    mma8(acc[mf][nf], ah[mf][0], ah[mf][1], ah[mf][2], ah[mf][3], bh0, bh1);
                }
            }
        }
        __syncthreads();
    }
#pragma unroll
    for (int mf = 0; mf < 4; mf++) {
        int r = row0 + wm * 64 + mf * 16 + (lane >> 2);
#pragma unroll
        for (int nf = 0; nf < 4; nf++) {
            int jl = wn * 32 + nf * 8 + (lane & 3) * 2;
            int jg = col0 + jl;
            float2 v0 = make_float2(acc[mf][nf][0] + sBias[jl], acc[mf][nf][1] + sBias[jl + 1]);
            float2 v1 = make_float2(acc[mf][nf][2] + sBias[jl], acc[mf][nf][3] + sBias[jl + 1]);
            *(float2*)&g_GBUF[(size_t)r * NGATE + jg] = v0;
            *(float2*)&g_GBUF[(size_t)(r + 8) * NGATE + jg] = v1;
        }
    }
}

// ---------------- persistent encoder layer (512 threads) ----------------
__global__ __launch_bounds__(512) void enc_layer_persistent(int layer)
{
    int tid = threadIdx.x, bid = blockIdx.x;
    int lane = tid & 31, w = tid >> 5;
    int wr = w & 7, wc = w >> 3;
    int q = lane & 3;
    const float* WH = layer ? g_e1H : g_e0H;
    const float* WL = layer ? g_e1L : g_e0L;

    g_henc[0][bid * 1024 + tid] = 0.f;
    g_henc[0][bid * 1024 + 512 + tid] = 0.f;
    sync_grid();

    __shared__ __align__(16) float sA[128 * 36];
    __shared__ __align__(16) float sBh[32 * 36];
    __shared__ __align__(16) float sBl[32 * 36];
    int dir = bid >> 6, jblk = bid & 63;
    int p_base = bid * 32;
    float* Hout = layer ? g_ENC : g_H1;
    float creg[2] = {0.f, 0.f};
    int r0 = wr * 16 + (lane >> 2);
    int rowp = (q & 1) ? (r0 + 8) : r0;

    for (int t = 0; t < LSEQ; t++) {
        int time = dir ? (LSEQ - 1 - t) : t;
        const float* A = g_henc[t & 1] + dir * NB * HE;
        float* Awr_ = g_henc[(t + 1) & 1] + dir * NB * HE;
        float acc[2][4] = {{0.f,0.f,0.f,0.f},{0.f,0.f,0.f,0.f}};

        for (int k0 = 0; k0 < HE; k0 += 32) {
#pragma unroll
            for (int p = 0; p < 2; p++) {
                int fi = tid + p * 512;
                int r = fi >> 3, c4 = fi & 7;
                *(float4*)&sA[r * 36 + c4 * 4] = *(const float4*)&A[r * HE + k0 + c4 * 4];
            }
            {
                int fi = tid & 255, r = fi >> 3, c4 = fi & 7;
                int nat = dir * 2048 + (r & 3) * 512 + jblk * 8 + (r >> 2);
                const float* src = (tid < 256 ? WH : WL) + (size_t)nat * HE + k0 + c4 * 4;
                float* dst = (tid < 256 ? sBh : sBl) + r * 36 + c4 * 4;
                *(float4*)dst = *(const float4*)src;
            }
            __syncthreads();
#pragma unroll
            for (int kk = 0; kk < 32; kk += 8) {
                int ac = kk + q;
                unsigned ah[4], al[4];
                tf32_split(sA[r0 * 36 + ac],           ah[0], al[0]);
                tf32_split(sA[(r0 + 8) * 36 + ac],     ah[1], al[1]);
                tf32_split(sA[r0 * 36 + ac + 4],       ah[2], al[2]);
                tf32_split(sA[(r0 + 8) * 36 + ac + 4], ah[3], al[3]);
#pragma unroll
                for (int nf = 0; nf < 2; nf++) {
                    int br = wc * 16 + nf * 8 + (lane >> 2);
                    unsigned bh0 = __float_as_uint(sBh[br * 36 + ac]);
                    unsigned bh1 = __float_as_uint(sBh[br * 36 + ac + 4]);
                    unsigned bl0 = __float_as_uint(sBl[br * 36 + ac]);
                    unsigned bl1 = __float_as_uint(sBl[br * 36 + ac + 4]);
                    mma8(acc[nf], al[0], al[1], al[2], al[3], bh0, bh1);
                    mma8(acc[nf], ah[0], ah[1], ah[2], ah[3], bl0, bl1);
                    mma8(acc[nf], ah[0], ah[1], ah[2], ah[3], bh0, bh1);
                }
            }
            __syncthreads();
        }
        // gate exchange (pairs share jj) + in-register pointwise
        {
            const float* Gin = g_GBUF + ((size_t)time * NB) * NGATE + p_base;
#pragma unroll
            for (int nf = 0; nf < 2; nf++) {
                float s0 = (q & 1) ? acc[nf][0] : acc[nf][2];
                float s1 = (q & 1) ? acc[nf][1] : acc[nf][3];
                float o0 = __shfl_xor_sync(0xffffffffu, s0, 1);
                float o1 = __shfl_xor_sync(0xffffffffu, s1, 1);
                float g0, g1, g2, g3;
                if (q & 1) { g0 = o0; g1 = o1; g2 = acc[nf][2]; g3 = acc[nf][3]; }
                else       { g0 = acc[nf][0]; g1 = acc[nf][1]; g2 = o0; g3 = o1; }
                int jj = wc * 4 + nf * 2 + (q >> 1);
                float4 G = *(const float4*)&Gin[(size_t)rowp * NGATE + jj * 4];
                float gi = g0 + G.x, gf = g1 + G.y, gg = g2 + G.z, go = g3 + G.w;
                float cc = creg[nf];
                cc = sigm(gf) * cc + sigm(gi) * tanhf(gg);
                float hh = sigm(go) * tanhf(cc);
                creg[nf] = cc;
                int j = jblk * 8 + jj;
                Awr_[rowp * HE + j] = hh;
                Hout[((size_t)time * NB + rowp) * HD + dir * HE + j] = hh;
            }
        }
        sync_grid();
    }
}

// ---------------- persistent decoder (512 threads) ----------------
__global__ __launch_bounds__(512) void dec_persistent(
    const float* __restrict__ bias, const float* __restrict__ wih,
    const float* __restrict__ out_w, const float* __restrict__ out_b,
    const int* __restrict__ tag_ids, float* __restrict__ prob_out)
{
    int tid = threadIdx.x, bid = blockIdx.x;
    int lane = tid & 31, w = tid >> 5;
    int wr = w & 7, wc = w >> 3;
    int q = lane & 3;
    int r0 = wr * 16 + (lane >> 2);
    int rowp = (q & 1) ? (r0 + 8) : r0;
    int j0 = bid * 8;

    g_hsum[0][bid * 1024 + tid] = g_ENC[bid * 1024 + tid];
    g_hsum[0][bid * 1024 + 512 + tid] = g_ENC[bid * 1024 + 512 + tid];
    if (bid == 0 && tid < NB) g_previdx[tid] = -1;
    if (bid == 0 && tid == 0) g_loss = 0.f;

    float creg[2], biasReg[2][4];
#pragma unroll
    for (int nf = 0; nf < 2; nf++) {
        int jj = wc * 4 + nf * 2 + (q >> 1);
        int j = j0 + jj;
        creg[nf] = g_ENC[(size_t)rowp * HD + HE + (j & (HE - 1))];
#pragma unroll
        for (int g = 0; g < 4; g++) biasReg[nf][g] = bias[g * HD + j];
    }
    sync_grid();

    __shared__ __align__(16) float sA[128 * 36];
    __shared__ __align__(16) float sBh[32 * 36];
    __shared__ __align__(16) float sBl[32 * 36];
    __shared__ float sh[HD];
    __shared__ float red[512];
    __shared__ float logitsS[TT];
    __shared__ float sLogZ;
    __shared__ int sArg;

    for (int t = 0; t < LSEQ; t++) {
        const float* Ain = g_hsum[t & 1];
        float* Anext = g_hsum[(t + 1) & 1];
        float acc[2][4] = {{0.f,0.f,0.f,0.f},{0.f,0.f,0.f,0.f}};

        for (int k0 = 0; k0 < HD; k0 += 32) {
#pragma unroll
            for (int p = 0; p < 2; p++) {
                int fi = tid + p * 512;
                int r = fi >> 3, c4 = fi & 7;
                *(float4*)&sA[r * 36 + c4 * 4] = *(const float4*)&Ain[(size_t)r * HD + k0 + c4 * 4];
            }
            {
                int fi = tid & 255, r = fi >> 3, c4 = fi & 7;
                int nat = (r & 3) * HD + j0 + (r >> 2);
                const float* src = (tid < 256 ? g_dH : g_dL) + (size_t)nat * HD + k0 + c4 * 4;
                float* dst = (tid < 256 ? sBh : sBl) + r * 36 + c4 * 4;
                *(float4*)dst = *(const float4*)src;
            }
            __syncthreads();
#pragma unroll
            for (int kk = 0; kk < 32; kk += 8) {
                int ac = kk + q;
                unsigned ah[4], al[4];
                tf32_split(sA[r0 * 36 + ac],           ah[0], al[0]);
                tf32_split(sA[(r0 + 8) * 36 + ac],     ah[1], al[1]);
                tf32_split(sA[r0 * 36 + ac + 4],       ah[2], al[2]);
                tf32_split(sA[(r0 + 8) * 36 + ac + 4], ah[3], al[3]);
#pragma unroll
                for (int nf = 0; nf < 2; nf++) {
                    int br = wc * 16 + nf * 8 + (lane >> 2);
                    unsigned bh0 = __float_as_uint(sBh[br * 36 + ac]);
                    unsigned bh1 = __float_as_uint(sBh[br * 36 + ac + 4]);
                    unsigned bl0 = __float_as_uint(sBl[br * 36 + ac]);
                    unsigned bl1 = __float_as_uint(sBl[br * 36 + ac + 4]);
                    mma8(acc[nf], al[0], al[1], al[2], al[3], bh0, bh1);
                    mma8(acc[nf], ah[0], ah[1], ah[2], ah[3], bl0, bl1);
                    mma8(acc[nf], ah[0], ah[1], ah[2], ah[3], bh0, bh1);
                }
            }
            __syncthreads();
        }
        // exchange + pointwise (+one-hot wih column, bias)
        {
            int pv = g_previdx[rowp];
#pragma unroll
            for (int nf = 0; nf < 2; nf++) {
                float s0 = (q & 1) ? acc[nf][0] : acc[nf][2];
                float s1 = (q & 1) ? acc[nf][1] : acc[nf][3];
                float o0 = __shfl_xor_sync(0xffffffffu, s0, 1);
                float o1 = __shfl_xor_sync(0xffffffffu, s1, 1);
                float g0, g1, g2, g3;
                if (q & 1) { g0 = o0; g1 = o1; g2 = acc[nf][2]; g3 = acc[nf][3]; }
                else       { g0 = acc[nf][0]; g1 = acc[nf][1]; g2 = o0; g3 = o1; }
                int jj = wc * 4 + nf * 2 + (q >> 1);
                int j = j0 + jj;
                float gi = g0 + biasReg[nf][0];
                float gf = g1 + biasReg[nf][1];
                float gg = g2 + biasReg[nf][2];
                float go = g3 + biasReg[nf][3];
                if (pv >= 0) {
                    gi += wih[(0 * HD + j) * TT + pv];
                    gf += wih[(1 * HD + j) * TT + pv];
                    gg += wih[(2 * HD + j) * TT + pv];
                    go += wih[(3 * HD + j) * TT + pv];
                }
                float cc = creg[nf];
                cc = sigm(gf) * cc + sigm(gi) * tanhf(gg);
                float hh = sigm(go) * tanhf(cc);
                creg[nf] = cc;
                g_hraw[rowp * HD + j] = hh;
                if (t + 1 < LSEQ)
                    Anext[(size_t)rowp * HD + j] = hh + g_ENC[((size_t)(t + 1) * NB + rowp) * HD + j];
            }
        }
        sync_grid();
        // logits + softmax + argmax + loss: CTA bid = batch row bid
        {
            int n = bid;
            sh[tid] = g_hraw[n * HD + tid];
            sh[tid + 512] = g_hraw[n * HD + tid + 512];
            __syncthreads();
            {
                int lj = tid & 127, quarter = tid >> 7;
                const float* wr_ = out_w + (size_t)lj * HD + quarter * 256;
                const float* hr = sh + quarter * 256;
                float s = 0.f;
#pragma unroll 8
                for (int k = 0; k < 256; k++) s += hr[k] * wr_[k];
                red[tid] = s;
            }
            __syncthreads();
            if (tid < TT)
                logitsS[tid] = red[tid] + red[tid + 128] + red[tid + 256] + red[tid + 384] + out_b[tid];
            __syncthreads();
            if (tid < 32) {
                float bv = -1e30f; int bi = 0;
#pragma unroll
                for (int p = 0; p < 4; p++) {
                    int k = tid + p * 32;
                    float v = logitsS[k];
                    if (v > bv) { bv = v; bi = k; }
                }
#pragma unroll
                for (int off = 16; off; off >>= 1) {
                    float ov = __shfl_down_sync(0xffffffffu, bv, off);
                    int   oi = __shfl_down_sync(0xffffffffu, bi, off);
                    if (ov > bv || (ov == bv && oi < bi)) { bv = ov; bi = oi; }
                }
                bv = __shfl_sync(0xffffffffu, bv, 0);
                bi = __shfl_sync(0xffffffffu, bi, 0);
                float s = 0.f;
#pragma unroll
                for (int p = 0; p < 4; p++) s += expf(logitsS[tid + p * 32] - bv);
#pragma unroll
                for (int off = 16; off; off >>= 1) s += __shfl_down_sync(0xffffffffu, s, off);
                if (tid == 0) { sLogZ = bv + logf(s); sArg = bi; }
            }
            __syncthreads();
            if (tid < TT)
                prob_out[(size_t)n * (LSEQ * TT) + t * TT + tid] = expf(logitsS[tid] - sLogZ);
            if (tid == 0) {
                g_previdx[n] = sArg;
                int tag = tag_ids[n * LSEQ + t];
                atomicAdd(&g_loss, -(logitsS[tag] - sLogZ) * (1.0f / NB));
            }
        }
        sync_grid();
    }
    if (bid == 0 && tid == 0) prob_out[(size_t)NB * LSEQ * TT] = g_loss;
}

// ---------------- launch: 8 graph nodes ----------------
extern "C" void kernel_launch(void* const* d_in, const int* in_sizes, int n_in,
                              void* d_out, int out_size)
{
    const int*   input_ids = (const int*)d_in[0];
    const int*   tag_ids   = (const int*)d_in[1];
    const float* embed     = (const float*)d_in[2];
    const float* e0_wih    = (const float*)d_in[3];
    const float* e0_whh    = (const float*)d_in[4];
    const float* e0_b      = (const float*)d_in[5];
    const float* e1_wih    = (const float*)d_in[6];
    const float* e1_whh    = (const float*)d_in[7];
    const float* e1_b      = (const float*)d_in[8];
    const float* dec_wih   = (const float*)d_in[9];
    const float* dec_whh   = (const float*)d_in[10];
    const float* dec_b     = (const float*)d_in[11];
    const float* out_w     = (const float*)d_in[12];
    const float* out_b     = (const float*)d_in[13];
    float* out = (float*)d_out;
    (void)in_sizes; (void)n_in; (void)out_size;

    split_sel<<<(2097152 + 255) / 256, 256>>>(e0_whh, 0, 2097152);
    split_sel<<<(2097152 + 255) / 256, 256>>>(e1_whh, 1, 2097152);
    split_sel<<<(4194304 + 255) / 256, 256>>>(dec_whh, 2, 4194304);

    dim3 ggrid(NGATE / 128, (LSEQ * NB) / 128);   // 32 x 160
    inproj_gemm<1, EMB><<<ggrid, 256>>>(e0_wih, e0_b, embed, input_ids);
    enc_layer_persistent<<<GRID, 512>>>(0);
    inproj_gemm<0, HD><<<ggrid, 256>>>(e1_wih, e1_b, embed, input_ids);
    enc_layer_persistent<<<GRID, 512>>>(1);
    dec_persistent<<<GRID, 512>>>(dec_b, dec_wih, out_w, out_b, tag_ids, out);
}

// round 12
// speedup vs baseline: 1.3578x; 1.1455x over previous
#include <cuda_runtime.h>
#include <cuda_fp16.h>
#include <cmath>

#define NB   128
#define LSEQ 160
#define EMB  512
#define HE   512
#define HD   1024
#define TT   128
#define NGATE 4096
#define GRID 128

// ---------------- scratch ----------------
static __device__ float g_GBUF[(size_t)LSEQ * NB * NGATE];   // inproj gates, permuted col = jblk*32 + jj*4 + gate
static __device__ float g_H1 [(size_t)LSEQ * NB * (2 * HE)];
static __device__ float g_ENC[(size_t)LSEQ * NB * (2 * HE)];
static __device__ float g_henc[2][2 * NB * HE];
static __device__ float g_hraw[NB * HD];
static __device__ float g_hsum[2][NB * HD];
static __device__ __align__(128) int   g_previdx[NB];
static __device__ __align__(128) float g_loss;
static __device__ __align__(128) unsigned g_arrive;
// pre-split fp16 hi/lo weight planes, packed 2 k-values per unsigned (natural row layout)
static __device__ unsigned g_e0H[1048576], g_e0L[1048576];   // enc0 whh  (2,2048,512)
static __device__ unsigned g_e1H[1048576], g_e1L[1048576];   // enc1 whh  (2,2048,512)
static __device__ unsigned g_dH [2097152], g_dL [2097152];   // dec whh   (4096,1024)
static __device__ unsigned g_i0H[1048576], g_i0L[1048576];   // enc0 wih  (2,2048,512)
static __device__ unsigned g_i1H[2097152], g_i1L[2097152];   // enc1 wih  (2,2048,1024)

__device__ __forceinline__ float sigm(float x) { return 1.0f / (1.0f + expf(-x)); }

// fp16x3 split: x = hi + lo exactly representable products; drop lo*lo (~2^-22)
__device__ __forceinline__ void h2_split(float x0, float x1, unsigned& hi, unsigned& lo) {
    __half2 h = __floats2half2_rn(x0, x1);
    float2 hf = __half22float2(h);
    __half2 l = __floats2half2_rn(x0 - hf.x, x1 - hf.y);
    hi = *reinterpret_cast<unsigned*>(&h);
    lo = *reinterpret_cast<unsigned*>(&l);
}
__device__ __forceinline__ void mma16(float* c, unsigned a0, unsigned a1, unsigned a2, unsigned a3,
                                      unsigned b0, unsigned b1) {
    asm volatile("mma.sync.aligned.m16n8k16.row.col.f32.f16.f16.f32 "
                 "{%0,%1,%2,%3}, {%4,%5,%6,%7}, {%8,%9}, {%0,%1,%2,%3};"
                 : "+f"(c[0]), "+f"(c[1]), "+f"(c[2]), "+f"(c[3])
                 : "r"(a0), "r"(a1), "r"(a2), "r"(a3), "r"(b0), "r"(b1));
}

// simple phase-bit grid barrier (R7-proven)
__device__ __forceinline__ void sync_grid()
{
    __syncthreads();
    if (threadIdx.x == 0) {
        unsigned add = (blockIdx.x == 0) ? (0x80000000u - (GRID - 1u)) : 1u;
        unsigned old, cur;
        asm volatile("atom.add.release.gpu.u32 %0, [%1], %2;"
                     : "=r"(old) : "l"(&g_arrive), "r"(add) : "memory");
        int spins = 0;
        for (;;) {
            asm volatile("ld.acquire.gpu.u32 %0, [%1];"
                         : "=r"(cur) : "l"(&g_arrive) : "memory");
            if ((old ^ cur) & 0x80000000u) break;
            if (++spins > 16) __nanosleep(64);
        }
    }
    __syncthreads();
}

// ---------------- weight pre-split (fp32 -> packed fp16 hi/lo pairs) ----------------
__global__ void split_pairs(const float* __restrict__ src, int which, int npairs)
{
    unsigned *h, *l;
    switch (which) {
        case 0:  h = g_e0H; l = g_e0L; break;
        case 1:  h = g_e1H; l = g_e1L; break;
        case 2:  h = g_dH;  l = g_dL;  break;
        case 3:  h = g_i0H; l = g_i0L; break;
        default: h = g_i1H; l = g_i1L; break;
    }
    int i = blockIdx.x * blockDim.x + threadIdx.x;
    if (i < npairs) {
        unsigned hi, lo;
        h2_split(src[2 * i], src[2 * i + 1], hi, lo);
        h[i] = hi; l[i] = lo;
    }
}

// ---------------- input-projection GEMM (fp16x3 mma k16), permuted cols ----------------
template <int GATHER, int K>
__global__ __launch_bounds__(256) void inproj_gemm(
    const float* __restrict__ bias,
    const float* __restrict__ embed, const int* __restrict__ ids)
{
    __shared__ float sA[128 * 20];
    __shared__ unsigned sBh[128 * 10];
    __shared__ unsigned sBl[128 * 10];
    __shared__ int   rowoff[128];
    __shared__ int   natrow[128];
    __shared__ float sBias[128];
    const unsigned* WH = GATHER ? g_i0H : g_i1H;
    const unsigned* WL = GATHER ? g_i0L : g_i1L;
    int tid = threadIdx.x;
    int row0 = blockIdx.y * 128;
    int col0 = blockIdx.x * 128;
    if (tid < 128) {
        int p = col0 + tid;
        int dir = p >> 11;
        int q2 = p & 2047;
        int c = q2 & 31;
        int nat = dir * 2048 + (c & 3) * 512 + (q2 >> 5) * 8 + (c >> 2);
        natrow[tid] = nat;
        sBias[tid] = bias[nat];
        if (GATHER) {
            int m = row0 + tid;
            rowoff[tid] = ids[(m & (NB - 1)) * LSEQ + (m >> 7)] * EMB;
        }
    }
    __syncthreads();
    int lane = tid & 31, w = tid >> 5;
    int wm = w >> 2, wn = w & 3, q = lane & 3;
    float acc[4][4][4];
#pragma unroll
    for (int a = 0; a < 4; a++)
#pragma unroll
        for (int b = 0; b < 4; b++)
#pragma unroll
            for (int c = 0; c < 4; c++) acc[a][b][c] = 0.f;

    for (int k0 = 0; k0 < K; k0 += 16) {
#pragma unroll
        for (int p = 0; p < 8; p++) {
            int idx = tid + p * 256;
            int r = idx >> 4, c = idx & 15;
            float v;
            if (GATHER) v = embed[rowoff[r] + k0 + c];
            else        v = g_H1[(size_t)(row0 + r) * K + k0 + c];
            sA[r * 20 + c] = v;
        }
#pragma unroll
        for (int p = 0; p < 4; p++) {
            int idx = tid + p * 256;          // 0..1023 : 128 rows x 8 pairs
            int r = idx >> 3, pi = idx & 7;
            size_t off = (size_t)natrow[r] * (K / 2) + (k0 >> 1) + pi;
            sBh[r * 10 + pi] = WH[off];
            sBl[r * 10 + pi] = WL[off];
        }
        __syncthreads();
        unsigned ah[4][4], al[4][4];
#pragma unroll
        for (int mf = 0; mf < 4; mf++) {
            int ar = wm * 64 + mf * 16 + (lane >> 2);
            float2 x;
            x = *(const float2*)&sA[ar * 20 + 2 * q];            h2_split(x.x, x.y, ah[mf][0], al[mf][0]);
            x = *(const float2*)&sA[(ar + 8) * 20 + 2 * q];      h2_split(x.x, x.y, ah[mf][1], al[mf][1]);
            x = *(const float2*)&sA[ar * 20 + 8 + 2 * q];        h2_split(x.x, x.y, ah[mf][2], al[mf][2]);
            x = *(const float2*)&sA[(ar + 8) * 20 + 8 + 2 * q];  h2_split(x.x, x.y, ah[mf][3], al[mf][3]);
        }
#pragma unroll
        for (int nf = 0; nf < 4; nf++) {
            int br = wn * 32 + nf * 8 + (lane >> 2);
            unsigned bh0 = sBh[br * 10 + q], bh1 = sBh[br * 10 + 4 + q];
            unsigned bl0 = sBl[br * 10 + q], bl1 = sBl[br * 10 + 4 + q];
#pragma unroll
            for (int mf = 0; mf < 4; mf++) {
                mma16(acc[mf][nf], al[mf][0], al[mf][1], al[mf][2], al[mf][3], bh0, bh1);
                mma16(acc[mf][nf], ah[mf][0], ah[mf][1], ah[mf][2], ah[mf][3], bl0, bl1);
                mma16(acc[mf][nf], ah[mf][0], ah[mf][1], ah[mf][2], ah[mf][3], bh0, bh1);
            }
        }
        __syncthreads();
    }
#pragma unroll
    for (int mf = 0; mf < 4; mf++) {
        int r = row0 + wm * 64 + mf * 16 + (lane >> 2);
#pragma unroll
        for (int nf = 0; nf < 4; nf++) {
            int jl = wn * 32 + nf * 8 + q * 2;
            int jg = col0 + jl;
            float2 v0 = make_float2(acc[mf][nf][0] + sBias[jl], acc[mf][nf][1] + sBias[jl + 1]);
            float2 v1 = make_float2(acc[mf][nf][2] + sBias[jl], acc[mf][nf][3] + sBias[jl + 1]);
            *(float2*)&g_GBUF[(size_t)r * NGATE + jg] = v0;
            *(float2*)&g_GBUF[(size_t)(r + 8) * NGATE + jg] = v1;
        }
    }
}

// ---------------- persistent encoder layer (512 threads, fp16x3 mma) ----------------
__global__ __launch_bounds__(512) void enc_layer_persistent(int layer)
{
    int tid = threadIdx.x, bid = blockIdx.x;
    int lane = tid & 31, w = tid >> 5;
    int wr = w & 7, wc = w >> 3;
    int q = lane & 3;
    const unsigned* WHp = layer ? g_e1H : g_e0H;
    const unsigned* WLp = layer ? g_e1L : g_e0L;

    g_henc[0][bid * 1024 + tid] = 0.f;
    g_henc[0][bid * 1024 + 512 + tid] = 0.f;
    sync_grid();

    __shared__ __align__(16) float sA[128 * 36];
    __shared__ unsigned sBh[32 * 18];
    __shared__ unsigned sBl[32 * 18];
    int dir = bid >> 6, jblk = bid & 63;
    int p_base = bid * 32;
    float* Hout = layer ? g_ENC : g_H1;
    float creg[2] = {0.f, 0.f};
    int r0 = wr * 16 + (lane >> 2);
    int rowp = (q & 1) ? (r0 + 8) : r0;

    for (int t = 0; t < LSEQ; t++) {
        int time = dir ? (LSEQ - 1 - t) : t;
        const float* A = g_henc[t & 1] + dir * NB * HE;
        float* Awr_ = g_henc[(t + 1) & 1] + dir * NB * HE;
        float acc[2][4] = {{0.f,0.f,0.f,0.f},{0.f,0.f,0.f,0.f}};

        for (int k0 = 0; k0 < HE; k0 += 32) {
#pragma unroll
            for (int p = 0; p < 2; p++) {
                int fi = tid + p * 512;
                int r = fi >> 3, c4 = fi & 7;
                *(float4*)&sA[r * 36 + c4 * 4] = *(const float4*)&A[r * HE + k0 + c4 * 4];
            }
            {
                int hf = tid >> 8;            // 0 -> hi plane, 1 -> lo plane
                int e = tid & 255;
#pragma unroll
                for (int p = 0; p < 2; p++) {
                    int idx = e + p * 256;    // 0..511 : 32 rows x 16 pairs
                    int r = idx >> 4, pi = idx & 15;
                    int nat = dir * 2048 + (r & 3) * 512 + jblk * 8 + (r >> 2);
                    unsigned v = (hf ? WLp : WHp)[(size_t)nat * (HE / 2) + (k0 >> 1) + pi];
                    (hf ? sBl : sBh)[r * 18 + pi] = v;
                }
            }
            __syncthreads();
#pragma unroll
            for (int kk = 0; kk < 2; kk++) {
                int kb = kk * 16;
                unsigned ah[4], al[4];
                float2 x;
                x = *(const float2*)&sA[r0 * 36 + kb + 2 * q];           h2_split(x.x, x.y, ah[0], al[0]);
                x = *(const float2*)&sA[(r0 + 8) * 36 + kb + 2 * q];     h2_split(x.x, x.y, ah[1], al[1]);
                x = *(const float2*)&sA[r0 * 36 + kb + 8 + 2 * q];       h2_split(x.x, x.y, ah[2], al[2]);
                x = *(const float2*)&sA[(r0 + 8) * 36 + kb + 8 + 2 * q]; h2_split(x.x, x.y, ah[3], al[3]);
#pragma unroll
                for (int nf = 0; nf < 2; nf++) {
                    int br = wc * 16 + nf * 8 + (lane >> 2);
                    unsigned bh0 = sBh[br * 18 + kk * 8 + q];
                    unsigned bh1 = sBh[br * 18 + kk * 8 + 4 + q];
                    unsigned bl0 = sBl[br * 18 + kk * 8 + q];
                    unsigned bl1 = sBl[br * 18 + kk * 8 + 4 + q];
                    mma16(acc[nf], al[0], al[1], al[2], al[3], bh0, bh1);
                    mma16(acc[nf], ah[0], ah[1], ah[2], ah[3], bl0, bl1);
                    mma16(acc[nf], ah[0], ah[1], ah[2], ah[3], bh0, bh1);
                }
            }
            __syncthreads();
        }
        // gate exchange (pairs share jj) + in-register pointwise
        {
            const float* Gin = g_GBUF + ((size_t)time * NB) * NGATE + p_base;
#pragma unroll
            for (int nf = 0; nf < 2; nf++) {
                float s0 = (q & 1) ? acc[nf][0] : acc[nf][2];
                float s1 = (q & 1) ? acc[nf][1] : acc[nf][3];
                float o0 = __shfl_xor_sync(0xffffffffu, s0, 1);
                float o1 = __shfl_xor_sync(0xffffffffu, s1, 1);
                float g0, g1, g2, g3;
                if (q & 1) { g0 = o0; g1 = o1; g2 = acc[nf][2]; g3 = acc[nf][3]; }
                else       { g0 = acc[nf][0]; g1 = acc[nf][1]; g2 = o0; g3 = o1; }
                int jj = wc * 4 + nf * 2 + (q >> 1);
                float4 G = *(const float4*)&Gin[(size_t)rowp * NGATE + jj * 4];
                float gi = g0 + G.x, gf = g1 + G.y, gg = g2 + G.z, go = g3 + G.w;
                float cc = creg[nf];
                cc = sigm(gf) * cc + sigm(gi) * tanhf(gg);
                float hh = sigm(go) * tanhf(cc);
                creg[nf] = cc;
                int j = jblk * 8 + jj;
                Awr_[rowp * HE + j] = hh;
                Hout[((size_t)time * NB + rowp) * HD + dir * HE + j] = hh;
            }
        }
        sync_grid();
    }
}

// ---------------- persistent decoder (512 threads, fp16x3 mma) ----------------
__global__ __launch_bounds__(512) void dec_persistent(
    const float* __restrict__ bias, const float* __restrict__ wih,
    const float* __restrict__ out_w, const float* __restrict__ out_b,
    const int* __restrict__ tag_ids, float* __restrict__ prob_out)
{
    int tid = threadIdx.x, bid = blockIdx.x;
    int lane = tid & 31, w = tid >> 5;
    int wr = w & 7, wc = w >> 3;
    int q = lane & 3;
    int r0 = wr * 16 + (lane >> 2);
    int rowp = (q & 1) ? (r0 + 8) : r0;
    int j0 = bid * 8;

    g_hsum[0][bid * 1024 + tid] = g_ENC[bid * 1024 + tid];
    g_hsum[0][bid * 1024 + 512 + tid] = g_ENC[bid * 1024 + 512 + tid];
    if (bid == 0 && tid < NB) g_previdx[tid] = -1;
    if (bid == 0 && tid == 0) g_loss = 0.f;

    float creg[2], biasReg[2][4];
#pragma unroll
    for (int nf = 0; nf < 2; nf++) {
        int jj = wc * 4 + nf * 2 + (q >> 1);
        int j = j0 + jj;
        creg[nf] = g_ENC[(size_t)rowp * HD + HE + (j & (HE - 1))];
#pragma unroll
        for (int g = 0; g < 4; g++) biasReg[nf][g] = bias[g * HD + j];
    }
    sync_grid();

    __shared__ __align__(16) float sA[128 * 36];
    __shared__ unsigned sBh[32 * 18];
    __shared__ unsigned sBl[32 * 18];
    __shared__ float sh[HD];
    __shared__ float red[512];
    __shared__ float logitsS[TT];
    __shared__ float sLogZ;
    __shared__ int sArg;

    for (int t = 0; t < LSEQ; t++) {
        const float* Ain = g_hsum[t & 1];
        float* Anext = g_hsum[(t + 1) & 1];
        float acc[2][4] = {{0.f,0.f,0.f,0.f},{0.f,0.f,0.f,0.f}};

        for (int k0 = 0; k0 < HD; k0 += 32) {
#pragma unroll
            for (int p = 0; p < 2; p++) {
                int fi = tid + p * 512;
                int r = fi >> 3, c4 = fi & 7;
                *(float4*)&sA[r * 36 + c4 * 4] = *(const float4*)&Ain[(size_t)r * HD + k0 + c4 * 4];
            }
            {
                int hf = tid >> 8;
                int e = tid & 255;
#pragma unroll
                for (int p = 0; p < 2; p++) {
                    int idx = e + p * 256;
                    int r = idx >> 4, pi = idx & 15;
                    int nat = (r & 3) * HD + j0 + (r >> 2);
                    unsigned v = (hf ? g_dL : g_dH)[(size_t)nat * (HD / 2) + (k0 >> 1) + pi];
                    (hf ? sBl : sBh)[r * 18 + pi] = v;
                }
            }
            __syncthreads();
#pragma unroll
            for (int kk = 0; kk < 2; kk++) {
                int kb = kk * 16;
                unsigned ah[4], al[4];
                float2 x;
                x = *(const float2*)&sA[r0 * 36 + kb + 2 * q];           h2_split(x.x, x.y, ah[0], al[0]);
                x = *(const float2*)&sA[(r0 + 8) * 36 + kb + 2 * q];     h2_split(x.x, x.y, ah[1], al[1]);
                x = *(const float2*)&sA[r0 * 36 + kb + 8 + 2 * q];       h2_split(x.x, x.y, ah[2], al[2]);
                x = *(const float2*)&sA[(r0 + 8) * 36 + kb + 8 + 2 * q]; h2_split(x.x, x.y, ah[3], al[3]);
#pragma unroll
                for (int nf = 0; nf < 2; nf++) {
                    int br = wc * 16 + nf * 8 + (lane >> 2);
                    unsigned bh0 = sBh[br * 18 + kk * 8 + q];
                    unsigned bh1 = sBh[br * 18 + kk * 8 + 4 + q];
                    unsigned bl0 = sBl[br * 18 + kk * 8 + q];
                    unsigned bl1 = sBl[br * 18 + kk * 8 + 4 + q];
                    mma16(acc[nf], al[0], al[1], al[2], al[3], bh0, bh1);
                    mma16(acc[nf], ah[0], ah[1], ah[2], ah[3], bl0, bl1);
                    mma16(acc[nf], ah[0], ah[1], ah[2], ah[3], bh0, bh1);
                }
            }
            __syncthreads();
        }
        // exchange + pointwise (+one-hot wih column, bias)
        {
            int pv = g_previdx[rowp];
#pragma unroll
            for (int nf = 0; nf < 2; nf++) {
                float s0 = (q & 1) ? acc[nf][0] : acc[nf][2];
                float s1 = (q & 1) ? acc[nf][1] : acc[nf][3];
                float o0 = __shfl_xor_sync(0xffffffffu, s0, 1);
                float o1 = __shfl_xor_sync(0xffffffffu, s1, 1);
                float g0, g1, g2, g3;
                if (q & 1) { g0 = o0; g1 = o1; g2 = acc[nf][2]; g3 = acc[nf][3]; }
                else       { g0 = acc[nf][0]; g1 = acc[nf][1]; g2 = o0; g3 = o1; }
                int jj = wc * 4 + nf * 2 + (q >> 1);
                int j = j0 + jj;
                float gi = g0 + biasReg[nf][0];
                float gf = g1 + biasReg[nf][1];
                float gg = g2 + biasReg[nf][2];
                float go = g3 + biasReg[nf][3];
                if (pv >= 0) {
                    gi += wih[(0 * HD + j) * TT + pv];
                    gf += wih[(1 * HD + j) * TT + pv];
                    gg += wih[(2 * HD + j) * TT + pv];
                    go += wih[(3 * HD + j) * TT + pv];
                }
                float cc = creg[nf];
                cc = sigm(gf) * cc + sigm(gi) * tanhf(gg);
                float hh = sigm(go) * tanhf(cc);
                creg[nf] = cc;
                g_hraw[rowp * HD + j] = hh;
                if (t + 1 < LSEQ)
                    Anext[(size_t)rowp * HD + j] = hh + g_ENC[((size_t)(t + 1) * NB + rowp) * HD + j];
            }
        }
        sync_grid();
        // logits + softmax + argmax + loss: CTA bid = batch row bid
        {
            int n = bid;
            sh[tid] = g_hraw[n * HD + tid];
            sh[tid + 512] = g_hraw[n * HD + tid + 512];
            __syncthreads();
            {
                int lj = tid & 127, quarter = tid >> 7;
                const float* wr_ = out_w + (size_t)lj * HD + quarter * 256;
                const float* hr = sh + quarter * 256;
                float s = 0.f;
#pragma unroll 8
                for (int k = 0; k < 256; k++) s += hr[k] * wr_[k];
                red[tid] = s;
            }
            __syncthreads();
            if (tid < TT)
                logitsS[tid] = red[tid] + red[tid + 128] + red[tid + 256] + red[tid + 384] + out_b[tid];
            __syncthreads();
            if (tid < 32) {
                float bv = -1e30f; int bi = 0;
#pragma unroll
                for (int p = 0; p < 4; p++) {
                    int k = tid + p * 32;
                    float v = logitsS[k];
                    if (v > bv) { bv = v; bi = k; }
                }
#pragma unroll
                for (int off = 16; off; off >>= 1) {
                    float ov = __shfl_down_sync(0xffffffffu, bv, off);
                    int   oi = __shfl_down_sync(0xffffffffu, bi, off);
                    if (ov > bv || (ov == bv && oi < bi)) { bv = ov; bi = oi; }
                }
                bv = __shfl_sync(0xffffffffu, bv, 0);
                bi = __shfl_sync(0xffffffffu, bi, 0);
                float s = 0.f;
#pragma unroll
                for (int p = 0; p < 4; p++) s += expf(logitsS[tid + p * 32] - bv);
#pragma unroll
                for (int off = 16; off; off >>= 1) s += __shfl_down_sync(0xffffffffu, s, off);
                if (tid == 0) { sLogZ = bv + logf(s); sArg = bi; }
            }
            __syncthreads();
            if (tid < TT)
                prob_out[(size_t)n * (LSEQ * TT) + t * TT + tid] = expf(logitsS[tid] - sLogZ);
            if (tid == 0) {
                g_previdx[n] = sArg;
                int tag = tag_ids[n * LSEQ + t];
                atomicAdd(&g_loss, -(logitsS[tag] - sLogZ) * (1.0f / NB));
            }
        }
        sync_grid();
    }
    if (bid == 0 && tid == 0) prob_out[(size_t)NB * LSEQ * TT] = g_loss;
}

// ---------------- launch: 10 graph nodes ----------------
extern "C" void kernel_launch(void* const* d_in, const int* in_sizes, int n_in,
                              void* d_out, int out_size)
{
    const int*   input_ids = (const int*)d_in[0];
    const int*   tag_ids   = (const int*)d_in[1];
    const float* embed     = (const float*)d_in[2];
    const float* e0_wih    = (const float*)d_in[3];
    const float* e0_whh    = (const float*)d_in[4];
    const float* e0_b      = (const float*)d_in[5];
    const float* e1_wih    = (const float*)d_in[6];
    const float* e1_whh    = (const float*)d_in[7];
    const float* e1_b      = (const float*)d_in[8];
    const float* dec_wih   = (const float*)d_in[9];
    const float* dec_whh   = (const float*)d_in[10];
    const float* dec_b     = (const float*)d_in[11];
    const float* out_w     = (const float*)d_in[12];
    const float* out_b     = (const float*)d_in[13];
    float* out = (float*)d_out;
    (void)in_sizes; (void)n_in; (void)out_size;

    split_pairs<<<4096, 256>>>(e0_whh, 0, 1048576);
    split_pairs<<<4096, 256>>>(e1_whh, 1, 1048576);
    split_pairs<<<8192, 256>>>(dec_whh, 2, 2097152);
    split_pairs<<<4096, 256>>>(e0_wih, 3, 1048576);
    split_pairs<<<8192, 256>>>(e1_wih, 4, 2097152);

    dim3 ggrid(NGATE / 128, (LSEQ * NB) / 128);   // 32 x 160
    inproj_gemm<1, EMB><<<ggrid, 256>>>(e0_b, embed, input_ids);
    enc_layer_persistent<<<GRID, 512>>>(0);
    inproj_gemm<0, HD><<<ggrid, 256>>>(e1_b, embed, input_ids);
    enc_layer_persistent<<<GRID, 512>>>(1);
    dec_persistent<<<GRID, 512>>>(dec_b, dec_wih, out_w, out_b, tag_ids, out);
}

// round 14
// speedup vs baseline: 1.3601x; 1.0017x over previous
#include <cuda_runtime.h>
#include <cuda_fp16.h>
#include <cmath>

#define NB   128
#define LSEQ 160
#define EMB  512
#define HE   512
#define HD   1024
#define TT   128
#define NGATE 4096
#define GRID 128

// ---------------- scratch ----------------
static __device__ float g_GBUF[(size_t)LSEQ * NB * NGATE];   // inproj gates, permuted col = jblk*32 + jj*4 + gate
static __device__ float g_H1 [(size_t)LSEQ * NB * (2 * HE)];
static __device__ float g_ENC[(size_t)LSEQ * NB * (2 * HE)];
static __device__ float g_henc[2][2 * NB * HE];
static __device__ float g_hraw[NB * HD];
static __device__ float g_hsum[2][NB * HD];
static __device__ __align__(128) int   g_previdx[NB];
static __device__ __align__(128) float g_loss;
static __device__ __align__(128) unsigned g_arrive;
// pre-split fp16 hi/lo weight planes, packed 2 k-values per unsigned (natural row layout)
static __device__ unsigned g_e0H[1048576], g_e0L[1048576];   // enc0 whh  (2,2048,512)
static __device__ unsigned g_e1H[1048576], g_e1L[1048576];   // enc1 whh  (2,2048,512)
static __device__ unsigned g_dH [2097152], g_dL [2097152];   // dec whh   (4096,1024)
static __device__ unsigned g_i0H[1048576], g_i0L[1048576];   // enc0 wih  (2,2048,512)
static __device__ unsigned g_i1H[2097152], g_i1L[2097152];   // enc1 wih  (2,2048,1024)

__device__ __forceinline__ float sigm(float x) { return 1.0f / (1.0f + expf(-x)); }

// fp16x3 split: x = hi + lo exactly representable products; drop lo*lo (~2^-22)
__device__ __forceinline__ void h2_split(float x0, float x1, unsigned& hi, unsigned& lo) {
    __half2 h = __floats2half2_rn(x0, x1);
    float2 hf = __half22float2(h);
    __half2 l = __floats2half2_rn(x0 - hf.x, x1 - hf.y);
    hi = *reinterpret_cast<unsigned*>(&h);
    lo = *reinterpret_cast<unsigned*>(&l);
}
__device__ __forceinline__ void mma16(float* c, unsigned a0, unsigned a1, unsigned a2, unsigned a3,
                                      unsigned b0, unsigned b1) {
    asm volatile("mma.sync.aligned.m16n8k16.row.col.f32.f16.f16.f32 "
                 "{%0,%1,%2,%3}, {%4,%5,%6,%7}, {%8,%9}, {%0,%1,%2,%3};"
                 : "+f"(c[0]), "+f"(c[1]), "+f"(c[2]), "+f"(c[3])
                 : "r"(a0), "r"(a1), "r"(a2), "r"(a3), "r"(b0), "r"(b1));
}

// simple phase-bit grid barrier (R7-proven)
__device__ __forceinline__ void sync_grid()
{
    __syncthreads();
    if (threadIdx.x == 0) {
        unsigned add = (blockIdx.x == 0) ? (0x80000000u - (GRID - 1u)) : 1u;
        unsigned old, cur;
        asm volatile("atom.add.release.gpu.u32 %0, [%1], %2;"
                     : "=r"(old) : "l"(&g_arrive), "r"(add) : "memory");
        int spins = 0;
        for (;;) {
            asm volatile("ld.acquire.gpu.u32 %0, [%1];"
                         : "=r"(cur) : "l"(&g_arrive) : "memory");
            if ((old ^ cur) & 0x80000000u) break;
            if (++spins > 16) __nanosleep(64);
        }
    }
    __syncthreads();
}

// ---------------- weight pre-split (fp32 -> packed fp16 hi/lo pairs) ----------------
__global__ void split_pairs(const float* __restrict__ src, int which, int npairs)
{
    unsigned *h, *l;
    switch (which) {
        case 0:  h = g_e0H; l = g_e0L; break;
        case 1:  h = g_e1H; l = g_e1L; break;
        case 2:  h = g_dH;  l = g_dL;  break;
        case 3:  h = g_i0H; l = g_i0L; break;
        default: h = g_i1H; l = g_i1L; break;
    }
    int i = blockIdx.x * blockDim.x + threadIdx.x;
    if (i < npairs) {
        unsigned hi, lo;
        h2_split(src[2 * i], src[2 * i + 1], hi, lo);
        h[i] = hi; l[i] = lo;
    }
}

// ---------------- input-projection GEMM (fp16x3 mma k16), permuted cols ----------------
template <int GATHER, int K>
__global__ __launch_bounds__(256) void inproj_gemm(
    const float* __restrict__ bias,
    const float* __restrict__ embed, const int* __restrict__ ids)
{
    __shared__ float sA[128 * 20];
    __shared__ unsigned sBh[128 * 10];
    __shared__ unsigned sBl[128 * 10];
    __shared__ int   rowoff[128];
    __shared__ int   natrow[128];
    __shared__ float sBias[128];
    const unsigned* WH = GATHER ? g_i0H : g_i1H;
    const unsigned* WL = GATHER ? g_i0L : g_i1L;
    int tid = threadIdx.x;
    int row0 = blockIdx.y * 128;
    int col0 = blockIdx.x * 128;
    if (tid < 128) {
        int p = col0 + tid;
        int dir = p >> 11;
        int q2 = p & 2047;
        int c = q2 & 31;
        int nat = dir * 2048 + (c & 3) * 512 + (q2 >> 5) * 8 + (c >> 2);
        natrow[tid] = nat;
        sBias[tid] = bias[nat];
        if (GATHER) {
            int m = row0 + tid;
            rowoff[tid] = ids[(m & (NB - 1)) * LSEQ + (m >> 7)] * EMB;
        }
    }
    __syncthreads();
    int lane = tid & 31, w = tid >> 5;
    int wm = w >> 2, wn = w & 3, q = lane & 3;
    float acc[4][4][4];
#pragma unroll
    for (int a = 0; a < 4; a++)
#pragma unroll
        for (int b = 0; b < 4; b++)
#pragma unroll
            for (int c = 0; c < 4; c++) acc[a][b][c] = 0.f;

    for (int k0 = 0; k0 < K; k0 += 16) {
#pragma unroll
        for (int p = 0; p < 8; p++) {
            int idx = tid + p * 256;
            int r = idx >> 4, c = idx & 15;
            float v;
            if (GATHER) v = embed[rowoff[r] + k0 + c];
            else        v = g_H1[(size_t)(row0 + r) * K + k0 + c];
            sA[r * 20 + c] = v;
        }
#pragma unroll
        for (int p = 0; p < 4; p++) {
            int idx = tid + p * 256;          // 0..1023 : 128 rows x 8 pairs
            int r = idx >> 3, pi = idx & 7;
            size_t off = (size_t)natrow[r] * (K / 2) + (k0 >> 1) + pi;
            sBh[r * 10 + pi] = WH[off];
            sBl[r * 10 + pi] = WL[off];
        }
        __syncthreads();
        unsigned ah[4][4], al[4][4];
#pragma unroll
        for (int mf = 0; mf < 4; mf++) {
            int ar = wm * 64 + mf * 16 + (lane >> 2);
            float2 x;
            x = *(const float2*)&sA[ar * 20 + 2 * q];            h2_split(x.x, x.y, ah[mf][0], al[mf][0]);
            x = *(const float2*)&sA[(ar + 8) * 20 + 2 * q];      h2_split(x.x, x.y, ah[mf][1], al[mf][1]);
            x = *(const float2*)&sA[ar * 20 + 8 + 2 * q];        h2_split(x.x, x.y, ah[mf][2], al[mf][2]);
            x = *(const float2*)&sA[(ar + 8) * 20 + 8 + 2 * q];  h2_split(x.x, x.y, ah[mf][3], al[mf][3]);
        }
#pragma unroll
        for (int nf = 0; nf < 4; nf++) {
            int br = wn * 32 + nf * 8 + (lane >> 2);
            unsigned bh0 = sBh[br * 10 + q], bh1 = sBh[br * 10 + 4 + q];
            unsigned bl0 = sBl[br * 10 + q], bl1 = sBl[br * 10 + 4 + q];
#pragma unroll
            for (int mf = 0; mf < 4; mf++) {
                mma16(acc[mf][nf], al[mf][0], al[mf][1], al[mf][2], al[mf][3], bh0, bh1);
                mma16(acc[mf][nf], ah[mf][0], ah[mf][1], ah[mf][2], ah[mf][3], bl0, bl1);
                mma16(acc[mf][nf], ah[mf][0], ah[mf][1], ah[mf][2], ah[mf][3], bh0, bh1);
            }
        }
        __syncthreads();
    }
#pragma unroll
    for (int mf = 0; mf < 4; mf++) {
        int r = row0 + wm * 64 + mf * 16 + (lane >> 2);
#pragma unroll
        for (int nf = 0; nf < 4; nf++) {
            int jl = wn * 32 + nf * 8 + q * 2;
            int jg = col0 + jl;
            float2 v0 = make_float2(acc[mf][nf][0] + sBias[jl], acc[mf][nf][1] + sBias[jl + 1]);
            float2 v1 = make_float2(acc[mf][nf][2] + sBias[jl], acc[mf][nf][3] + sBias[jl + 1]);
            *(float2*)&g_GBUF[(size_t)r * NGATE + jg] = v0;
            *(float2*)&g_GBUF[(size_t)(r + 8) * NGATE + jg] = v1;
        }
    }
}

// ---------------- persistent encoder layer (512 threads, fp16x3 mma) ----------------
__global__ __launch_bounds__(512) void enc_layer_persistent(int layer)
{
    int tid = threadIdx.x, bid = blockIdx.x;
    int lane = tid & 31, w = tid >> 5;
    int wr = w & 7, wc = w >> 3;
    int q = lane & 3;
    const unsigned* WHp = layer ? g_e1H : g_e0H;
    const unsigned* WLp = layer ? g_e1L : g_e0L;

    g_henc[0][bid * 1024 + tid] = 0.f;
    g_henc[0][bid * 1024 + 512 + tid] = 0.f;
    sync_grid();

    __shared__ __align__(16) float sA[128 * 36];
    __shared__ unsigned sBh[32 * 18];
    __shared__ unsigned sBl[32 * 18];
    int dir = bid >> 6, jblk = bid & 63;
    int p_base = bid * 32;
    float* Hout = layer ? g_ENC : g_H1;
    float creg[2] = {0.f, 0.f};
    int r0 = wr * 16 + (lane >> 2);
    int rowp = (q & 1) ? (r0 + 8) : r0;

    for (int t = 0; t < LSEQ; t++) {
        int time = dir ? (LSEQ - 1 - t) : t;
        const float* A = g_henc[t & 1] + dir * NB * HE;
        float* Awr_ = g_henc[(t + 1) & 1] + dir * NB * HE;
        float acc[2][4] = {{0.f,0.f,0.f,0.f},{0.f,0.f,0.f,0.f}};

        for (int k0 = 0; k0 < HE; k0 += 32) {
#pragma unroll
            for (int p = 0; p < 2; p++) {
                int fi = tid + p * 512;
                int r = fi >> 3, c4 = fi & 7;
                *(float4*)&sA[r * 36 + c4 * 4] = *(const float4*)&A[r * HE + k0 + c4 * 4];
            }
            {
                int hf = tid >> 8;            // 0 -> hi plane, 1 -> lo plane
                int e = tid & 255;
#pragma unroll
                for (int p = 0; p < 2; p++) {
                    int idx = e + p * 256;    // 0..511 : 32 rows x 16 pairs
                    int r = idx >> 4, pi = idx & 15;
                    int nat = dir * 2048 + (r & 3) * 512 + jblk * 8 + (r >> 2);
                    unsigned v = (hf ? WLp : WHp)[(size_t)nat * (HE / 2) + (k0 >> 1) + pi];
                    (hf ? sBl : sBh)[r * 18 + pi] = v;
                }
            }
            __syncthreads();
#pragma unroll
            for (int kk = 0; kk < 2; kk++) {
                int kb = kk * 16;
                unsigned ah[4], al[4];
                float2 x;
                x = *(const float2*)&sA[r0 * 36 + kb + 2 * q];           h2_split(x.x, x.y, ah[0], al[0]);
                x = *(const float2*)&sA[(r0 + 8) * 36 + kb + 2 * q];     h2_split(x.x, x.y, ah[1], al[1]);
                x = *(const float2*)&sA[r0 * 36 + kb + 8 + 2 * q];       h2_split(x.x, x.y, ah[2], al[2]);
                x = *(const float2*)&sA[(r0 + 8) * 36 + kb + 8 + 2 * q]; h2_split(x.x, x.y, ah[3], al[3]);
#pragma unroll
                for (int nf = 0; nf < 2; nf++) {
                    int br = wc * 16 + nf * 8 + (lane >> 2);
                    unsigned bh0 = sBh[br * 18 + kk * 8 + q];
                    unsigned bh1 = sBh[br * 18 + kk * 8 + 4 + q];
                    unsigned bl0 = sBl[br * 18 + kk * 8 + q];
                    unsigned bl1 = sBl[br * 18 + kk * 8 + 4 + q];
                    mma16(acc[nf], al[0], al[1], al[2], al[3], bh0, bh1);
                    mma16(acc[nf], ah[0], ah[1], ah[2], ah[3], bl0, bl1);
                    mma16(acc[nf], ah[0], ah[1], ah[2], ah[3], bh0, bh1);
                }
            }
            __syncthreads();
        }
        // gate exchange (pairs share jj) + in-register pointwise
        {
            const float* Gin = g_GBUF + ((size_t)time * NB) * NGATE + p_base;
#pragma unroll
            for (int nf = 0; nf < 2; nf++) {
                float s0 = (q & 1) ? acc[nf][0] : acc[nf][2];
                float s1 = (q & 1) ? acc[nf][1] : acc[nf][3];
                float o0 = __shfl_xor_sync(0xffffffffu, s0, 1);
                float o1 = __shfl_xor_sync(0xffffffffu, s1, 1);
                float g0, g1, g2, g3;
                if (q & 1) { g0 = o0; g1 = o1; g2 = acc[nf][2]; g3 = acc[nf][3]; }
                else       { g0 = acc[nf][0]; g1 = acc[nf][1]; g2 = o0; g3 = o1; }
                int jj = wc * 4 + nf * 2 + (q >> 1);
                float4 G = *(const float4*)&Gin[(size_t)rowp * NGATE + jj * 4];
                float gi = g0 + G.x, gf = g1 + G.y, gg = g2 + G.z, go = g3 + G.w;
                float cc = creg[nf];
                cc = sigm(gf) * cc + sigm(gi) * tanhf(gg);
                float hh = sigm(go) * tanhf(cc);
                creg[nf] = cc;
                int j = jblk * 8 + jj;
                Awr_[rowp * HE + j] = hh;
                Hout[((size_t)time * NB + rowp) * HD + dir * HE + j] = hh;
            }
        }
        sync_grid();
    }
}

// ---------------- persistent decoder (512 threads, fp16x3 mma) ----------------
__global__ __launch_bounds__(512) void dec_persistent(
    const float* __restrict__ bias, const float* __restrict__ wih,
    const float* __restrict__ out_w, const float* __restrict__ out_b,
    const int* __restrict__ tag_ids, float* __restrict__ prob_out)
{
    int tid = threadIdx.x, bid = blockIdx.x;
    int lane = tid & 31, w = tid >> 5;
    int wr = w & 7, wc = w >> 3;
    int q = lane & 3;
    int r0 = wr * 16 + (lane >> 2);
    int rowp = (q & 1) ? (r0 + 8) : r0;
    int j0 = bid * 8;

    g_hsum[0][bid * 1024 + tid] = g_ENC[bid * 1024 + tid];
    g_hsum[0][bid * 1024 + 512 + tid] = g_ENC[bid * 1024 + 512 + tid];
    if (bid == 0 && tid < NB) g_previdx[tid] = -1;
    if (bid == 0 && tid == 0) g_loss = 0.f;

    float creg[2], biasReg[2][4];
#pragma unroll
    for (int nf = 0; nf < 2; nf++) {
        int jj = wc * 4 + nf * 2 + (q >> 1);
        int j = j0 + jj;
        creg[nf] = g_ENC[(size_t)rowp * HD + HE + (j & (HE - 1))];
#pragma unroll
        for (int g = 0; g < 4; g++) biasReg[nf][g] = bias[g * HD + j];
    }
    sync_grid();

    __shared__ __align__(16) float sA[128 * 36];
    __shared__ unsigned sBh[32 * 18];
    __shared__ unsigned sBl[32 * 18];
    __shared__ float sh[HD];
    __shared__ float red[512];
    __shared__ float logitsS[TT];
    __shared__ float sLogZ;
    __shared__ int sArg;

    for (int t = 0; t < LSEQ; t++) {
        const float* Ain = g_hsum[t & 1];
        float* Anext = g_hsum[(t + 1) & 1];
        float acc[2][4] = {{0.f,0.f,0.f,0.f},{0.f,0.f,0.f,0.f}};

        for (int k0 = 0; k0 < HD; k0 += 32) {
#pragma unroll
            for (int p = 0; p < 2; p++) {
                int fi = tid + p * 512;
                int r = fi >> 3, c4 = fi & 7;
                *(float4*)&sA[r * 36 + c4 * 4] = *(const float4*)&Ain[(size_t)r * HD + k0 + c4 * 4];
            }
            {
                int hf = tid >> 8;
                int e = tid & 255;
#pragma unroll
                for (int p = 0; p < 2; p++) {
                    int idx = e + p * 256;
                    int r = idx >> 4, pi = idx & 15;
                    int nat = (r & 3) * HD + j0 + (r >> 2);
                    unsigned v = (hf ? g_dL : g_dH)[(size_t)nat * (HD / 2) + (k0 >> 1) + pi];
                    (hf ? sBl : sBh)[r * 18 + pi] = v;
                }
            }
            __syncthreads();
#pragma unroll
            for (int kk = 0; kk < 2; kk++) {
                int kb = kk * 16;
                unsigned ah[4], al[4];
                float2 x;
                x = *(const float2*)&sA[r0 * 36 + kb + 2 * q];           h2_split(x.x, x.y, ah[0], al[0]);
                x = *(const float2*)&sA[(r0 + 8) * 36 + kb + 2 * q];     h2_split(x.x, x.y, ah[1], al[1]);
                x = *(const float2*)&sA[r0 * 36 + kb + 8 + 2 * q];       h2_split(x.x, x.y, ah[2], al[2]);
                x = *(const float2*)&sA[(r0 + 8) * 36 + kb + 8 + 2 * q]; h2_split(x.x, x.y, ah[3], al[3]);
#pragma unroll
                for (int nf = 0; nf < 2; nf++) {
                    int br = wc * 16 + nf * 8 + (lane >> 2);
                    unsigned bh0 = sBh[br * 18 + kk * 8 + q];
                    unsigned bh1 = sBh[br * 18 + kk * 8 + 4 + q];
                    unsigned bl0 = sBl[br * 18 + kk * 8 + q];
                    unsigned bl1 = sBl[br * 18 + kk * 8 + 4 + q];
                    mma16(acc[nf], al[0], al[1], al[2], al[3], bh0, bh1);
                    mma16(acc[nf], ah[0], ah[1], ah[2], ah[3], bl0, bl1);
                    mma16(acc[nf], ah[0], ah[1], ah[2], ah[3], bh0, bh1);
                }
            }
            __syncthreads();
        }
        // exchange + pointwise (+one-hot wih column, bias)
        {
            int pv = g_previdx[rowp];
#pragma unroll
            for (int nf = 0; nf < 2; nf++) {
                float s0 = (q & 1) ? acc[nf][0] : acc[nf][2];
                float s1 = (q & 1) ? acc[nf][1] : acc[nf][3];
                float o0 = __shfl_xor_sync(0xffffffffu, s0, 1);
                float o1 = __shfl_xor_sync(0xffffffffu, s1, 1);
                float g0, g1, g2, g3;
                if (q & 1) { g0 = o0; g1 = o1; g2 = acc[nf][2]; g3 = acc[nf][3]; }
                else       { g0 = acc[nf][0]; g1 = acc[nf][1]; g2 = o0; g3 = o1; }
                int jj = wc * 4 + nf * 2 + (q >> 1);
                int j = j0 + jj;
                float gi = g0 + biasReg[nf][0];
                float gf = g1 + biasReg[nf][1];
                float gg = g2 + biasReg[nf][2];
                float go = g3 + biasReg[nf][3];
                if (pv >= 0) {
                    gi += wih[(0 * HD + j) * TT + pv];
                    gf += wih[(1 * HD + j) * TT + pv];
                    gg += wih[(2 * HD + j) * TT + pv];
                    go += wih[(3 * HD + j) * TT + pv];
                }
                float cc = creg[nf];
                cc = sigm(gf) * cc + sigm(gi) * tanhf(gg);
                float hh = sigm(go) * tanhf(cc);
                creg[nf] = cc;
                g_hraw[rowp * HD + j] = hh;
                if (t + 1 < LSEQ)
                    Anext[(size_t)rowp * HD + j] = hh + g_ENC[((size_t)(t + 1) * NB + rowp) * HD + j];
            }
        }
        sync_grid();
        // logits + softmax + argmax + loss: CTA bid = batch row bid
        {
            int n = bid;
            sh[tid] = g_hraw[n * HD + tid];
            sh[tid + 512] = g_hraw[n * HD + tid + 512];
            __syncthreads();
            {
                int lj = tid & 127, quarter = tid >> 7;
                const float* wr_ = out_w + (size_t)lj * HD + quarter * 256;
                const float* hr = sh + quarter * 256;
                float s = 0.f;
#pragma unroll 8
                for (int k = 0; k < 256; k++) s += hr[k] * wr_[k];
                red[tid] = s;
            }
            __syncthreads();
            if (tid < TT)
                logitsS[tid] = red[tid] + red[tid + 128] + red[tid + 256] + red[tid + 384] + out_b[tid];
            __syncthreads();
            if (tid < 32) {
                float bv = -1e30f; int bi = 0;
#pragma unroll
                for (int p = 0; p < 4; p++) {
                    int k = tid + p * 32;
                    float v = logitsS[k];
                    if (v > bv) { bv = v; bi = k; }
                }
#pragma unroll
                for (int off = 16; off; off >>= 1) {
                    float ov = __shfl_down_sync(0xffffffffu, bv, off);
                    int   oi = __shfl_down_sync(0xffffffffu, bi, off);
                    if (ov > bv || (ov == bv && oi < bi)) { bv = ov; bi = oi; }
                }
                bv = __shfl_sync(0xffffffffu, bv, 0);
                bi = __shfl_sync(0xffffffffu, bi, 0);
                float s = 0.f;
#pragma unroll
                for (int p = 0; p < 4; p++) s += expf(logitsS[tid + p * 32] - bv);
#pragma unroll
                for (int off = 16; off; off >>= 1) s += __shfl_down_sync(0xffffffffu, s, off);
                if (tid == 0) { sLogZ = bv + logf(s); sArg = bi; }
            }
            __syncthreads();
            if (tid < TT)
                prob_out[(size_t)n * (LSEQ * TT) + t * TT + tid] = expf(logitsS[tid] - sLogZ);
            if (tid == 0) {
                g_previdx[n] = sArg;
                int tag = tag_ids[n * LSEQ + t];
                atomicAdd(&g_loss, -(logitsS[tag] - sLogZ) * (1.0f / NB));
            }
        }
        sync_grid();
    }
    if (bid == 0 && tid == 0) prob_out[(size_t)NB * LSEQ * TT] = g_loss;
}

// ---------------- launch: 10 graph nodes ----------------
extern "C" void kernel_launch(void* const* d_in, const int* in_sizes, int n_in,
                              void* d_out, int out_size)
{
    const int*   input_ids = (const int*)d_in[0];
    const int*   tag_ids   = (const int*)d_in[1];
    const float* embed     = (const float*)d_in[2];
    const float* e0_wih    = (const float*)d_in[3];
    const float* e0_whh    = (const float*)d_in[4];
    const float* e0_b      = (const float*)d_in[5];
    const float* e1_wih    = (const float*)d_in[6];
    const float* e1_whh    = (const float*)d_in[7];
    const float* e1_b      = (const float*)d_in[8];
    const float* dec_wih   = (const float*)d_in[9];
    const float* dec_whh   = (const float*)d_in[10];
    const float* dec_b     = (const float*)d_in[11];
    const float* out_w     = (const float*)d_in[12];
    const float* out_b     = (const float*)d_in[13];
    float* out = (float*)d_out;
    (void)in_sizes; (void)n_in; (void)out_size;

    split_pairs<<<4096, 256>>>(e0_whh, 0, 1048576);
    split_pairs<<<4096, 256>>>(e1_whh, 1, 1048576);
    split_pairs<<<8192, 256>>>(dec_whh, 2, 2097152);
    split_pairs<<<4096, 256>>>(e0_wih, 3, 1048576);
    split_pairs<<<8192, 256>>>(e1_wih, 4, 2097152);

    dim3 ggrid(NGATE / 128, (LSEQ * NB) / 128);   // 32 x 160
    inproj_gemm<1, EMB><<<ggrid, 256>>>(e0_b, embed, input_ids);
    enc_layer_persistent<<<GRID, 512>>>(0);
    inproj_gemm<0, HD><<<ggrid, 256>>>(e1_b, embed, input_ids);
    enc_layer_persistent<<<GRID, 512>>>(1);
    dec_persistent<<<GRID, 512>>>(dec_b, dec_wih, out_w, out_b, tag_ids, out);
}

// round 16
// speedup vs baseline: 1.5779x; 1.1602x over previous
#include <cuda_runtime.h>
#include <cuda_fp16.h>
#include <cmath>

#define NB   128
#define LSEQ 160
#define EMB  512
#define HE   512
#define HD   1024
#define TT   128
#define NGATE 4096
#define GRID 128

// ---------------- scratch ----------------
static __device__ float g_GBUF[(size_t)LSEQ * NB * NGATE];   // inproj gates, permuted col = jblk*32 + jj*4 + gate
static __device__ float g_H1 [(size_t)LSEQ * NB * (2 * HE)];
static __device__ float g_ENC[(size_t)LSEQ * NB * (2 * HE)];
static __device__ float g_henc[2][2 * NB * HE];
static __device__ float g_hraw[NB * HD];
static __device__ float g_hsum[2][NB * HD];
static __device__ __align__(128) int   g_previdx[NB];
static __device__ __align__(128) float g_loss;
static __device__ __align__(128) unsigned g_arrive;
// pre-split fp16 hi/lo weight planes, packed 2 k-values per unsigned (natural row layout)
static __device__ unsigned g_e0H[1048576], g_e0L[1048576];   // enc0 whh  (2,2048,512)
static __device__ unsigned g_e1H[1048576], g_e1L[1048576];   // enc1 whh  (2,2048,512)
static __device__ unsigned g_dH [2097152], g_dL [2097152];   // dec whh   (4096,1024)
static __device__ unsigned g_i0H[1048576], g_i0L[1048576];   // enc0 wih  (2,2048,512)
static __device__ unsigned g_i1H[2097152], g_i1L[2097152];   // enc1 wih  (2,2048,1024)

__device__ __forceinline__ float sigm(float x) { return 1.0f / (1.0f + expf(-x)); }

// fp16x3 split: x = hi + lo; dropped lo*lo term ~2^-22
__device__ __forceinline__ void h2_split(float x0, float x1, unsigned& hi, unsigned& lo) {
    __half2 h = __floats2half2_rn(x0, x1);
    float2 hf = __half22float2(h);
    __half2 l = __floats2half2_rn(x0 - hf.x, x1 - hf.y);
    hi = *reinterpret_cast<unsigned*>(&h);
    lo = *reinterpret_cast<unsigned*>(&l);
}
__device__ __forceinline__ void mma16(float* c, unsigned a0, unsigned a1, unsigned a2, unsigned a3,
                                      unsigned b0, unsigned b1) {
    asm volatile("mma.sync.aligned.m16n8k16.row.col.f32.f16.f16.f32 "
                 "{%0,%1,%2,%3}, {%4,%5,%6,%7}, {%8,%9}, {%0,%1,%2,%3};"
                 : "+f"(c[0]), "+f"(c[1]), "+f"(c[2]), "+f"(c[3])
                 : "r"(a0), "r"(a1), "r"(a2), "r"(a3), "r"(b0), "r"(b1));
}

// simple phase-bit grid barrier (R7-proven)
__device__ __forceinline__ void sync_grid()
{
    __syncthreads();
    if (threadIdx.x == 0) {
        unsigned add = (blockIdx.x == 0) ? (0x80000000u - (GRID - 1u)) : 1u;
        unsigned old, cur;
        asm volatile("atom.add.release.gpu.u32 %0, [%1], %2;"
                     : "=r"(old) : "l"(&g_arrive), "r"(add) : "memory");
        int spins = 0;
        for (;;) {
            asm volatile("ld.acquire.gpu.u32 %0, [%1];"
                         : "=r"(cur) : "l"(&g_arrive) : "memory");
            if ((old ^ cur) & 0x80000000u) break;
            if (++spins > 16) __nanosleep(64);
        }
    }
    __syncthreads();
}

// ---------------- weight pre-split ----------------
__global__ void split_pairs(const float* __restrict__ src, int which, int npairs)
{
    unsigned *h, *l;
    switch (which) {
        case 0:  h = g_e0H; l = g_e0L; break;
        case 1:  h = g_e1H; l = g_e1L; break;
        case 2:  h = g_dH;  l = g_dL;  break;
        case 3:  h = g_i0H; l = g_i0L; break;
        default: h = g_i1H; l = g_i1L; break;
    }
    int i = blockIdx.x * blockDim.x + threadIdx.x;
    if (i < npairs) {
        unsigned hi, lo;
        h2_split(src[2 * i], src[2 * i + 1], hi, lo);
        h[i] = hi; l[i] = lo;
    }
}

// ---------------- input-projection GEMM (fp16x3 mma k16), permuted cols ----------------
template <int GATHER, int K>
__global__ __launch_bounds__(256, 2) void inproj_gemm(
    const float* __restrict__ bias,
    const float* __restrict__ embed, const int* __restrict__ ids)
{
    __shared__ float sA[128 * 20];
    __shared__ unsigned sBh[128 * 10];
    __shared__ unsigned sBl[128 * 10];
    __shared__ int   rowoff[128];
    __shared__ int   natrow[128];
    __shared__ float sBias[128];
    const unsigned* WH = GATHER ? g_i0H : g_i1H;
    const unsigned* WL = GATHER ? g_i0L : g_i1L;
    int tid = threadIdx.x;
    int row0 = blockIdx.y * 128;
    int col0 = blockIdx.x * 128;
    if (tid < 128) {
        int p = col0 + tid;
        int dir = p >> 11;
        int q2 = p & 2047;
        int c = q2 & 31;
        int nat = dir * 2048 + (c & 3) * 512 + (q2 >> 5) * 8 + (c >> 2);
        natrow[tid] = nat;
        sBias[tid] = bias[nat];
        if (GATHER) {
            int m = row0 + tid;
            rowoff[tid] = ids[(m & (NB - 1)) * LSEQ + (m >> 7)] * EMB;
        }
    }
    __syncthreads();
    int lane = tid & 31, w = tid >> 5;
    int wm = w >> 2, wn = w & 3, q = lane & 3;
    float acc[4][4][4];
#pragma unroll
    for (int a = 0; a < 4; a++)
#pragma unroll
        for (int b = 0; b < 4; b++)
#pragma unroll
            for (int c = 0; c < 4; c++) acc[a][b][c] = 0.f;

    for (int k0 = 0; k0 < K; k0 += 16) {
#pragma unroll
        for (int p = 0; p < 8; p++) {
            int idx = tid + p * 256;
            int r = idx >> 4, c = idx & 15;
            float v;
            if (GATHER) v = embed[rowoff[r] + k0 + c];
            else        v = g_H1[(size_t)(row0 + r) * K + k0 + c];
            sA[r * 20 + c] = v;
        }
#pragma unroll
        for (int p = 0; p < 4; p++) {
            int idx = tid + p * 256;
            int r = idx >> 3, pi = idx & 7;
            size_t off = (size_t)natrow[r] * (K / 2) + (k0 >> 1) + pi;
            sBh[r * 10 + pi] = WH[off];
            sBl[r * 10 + pi] = WL[off];
        }
        __syncthreads();
        unsigned ah[4][4], al[4][4];
#pragma unroll
        for (int mf = 0; mf < 4; mf++) {
            int ar = wm * 64 + mf * 16 + (lane >> 2);
            float2 x;
            x = *(const float2*)&sA[ar * 20 + 2 * q];            h2_split(x.x, x.y, ah[mf][0], al[mf][0]);
            x = *(const float2*)&sA[(ar + 8) * 20 + 2 * q];      h2_split(x.x, x.y, ah[mf][1], al[mf][1]);
            x = *(const float2*)&sA[ar * 20 + 8 + 2 * q];        h2_split(x.x, x.y, ah[mf][2], al[mf][2]);
            x = *(const float2*)&sA[(ar + 8) * 20 + 8 + 2 * q];  h2_split(x.x, x.y, ah[mf][3], al[mf][3]);
        }
#pragma unroll
        for (int nf = 0; nf < 4; nf++) {
            int br = wn * 32 + nf * 8 + (lane >> 2);
            unsigned bh0 = sBh[br * 10 + q], bh1 = sBh[br * 10 + 4 + q];
            unsigned bl0 = sBl[br * 10 + q], bl1 = sBl[br * 10 + 4 + q];
#pragma unroll
            for (int mf = 0; mf < 4; mf++) {
                mma16(acc[mf][nf], al[mf][0], al[mf][1], al[mf][2], al[mf][3], bh0, bh1);
                mma16(acc[mf][nf], ah[mf][0], ah[mf][1], ah[mf][2], ah[mf][3], bl0, bl1);
                mma16(acc[mf][nf], ah[mf][0], ah[mf][1], ah[mf][2], ah[mf][3], bh0, bh1);
            }
        }
        __syncthreads();
    }
#pragma unroll
    for (int mf = 0; mf < 4; mf++) {
        int r = row0 + wm * 64 + mf * 16 + (lane >> 2);
#pragma unroll
        for (int nf = 0; nf < 4; nf++) {
            int jl = wn * 32 + nf * 8 + q * 2;
            int jg = col0 + jl;
            float2 v0 = make_float2(acc[mf][nf][0] + sBias[jl], acc[mf][nf][1] + sBias[jl + 1]);
            float2 v1 = make_float2(acc[mf][nf][2] + sBias[jl], acc[mf][nf][3] + sBias[jl + 1]);
            *(float2*)&g_GBUF[(size_t)r * NGATE + jg] = v0;
            *(float2*)&g_GBUF[(size_t)(r + 8) * NGATE + jg] = v1;
        }
    }
}

// ---------------- persistent encoder layer (512 threads, term-split accumulators) ----------------
__global__ __launch_bounds__(512) void enc_layer_persistent(int layer)
{
    int tid = threadIdx.x, bid = blockIdx.x;
    int lane = tid & 31, w = tid >> 5;
    int wr = w & 7, wc = w >> 3;
    int q = lane & 3;
    const unsigned* WHp = layer ? g_e1H : g_e0H;
    const unsigned* WLp = layer ? g_e1L : g_e0L;

    g_henc[0][bid * 1024 + tid] = 0.f;
    g_henc[0][bid * 1024 + 512 + tid] = 0.f;
    sync_grid();

    __shared__ __align__(16) float sA[128 * 36];
    __shared__ unsigned sBh[32 * 18];
    __shared__ unsigned sBl[32 * 18];
    int dir = bid >> 6, jblk = bid & 63;
    int p_base = bid * 32;
    float* Hout = layer ? g_ENC : g_H1;
    float creg[2] = {0.f, 0.f};
    int r0 = wr * 16 + (lane >> 2);
    int rowp = (q & 1) ? (r0 + 8) : r0;

    for (int t = 0; t < LSEQ; t++) {
        int time = dir ? (LSEQ - 1 - t) : t;
        const float* A = g_henc[t & 1] + dir * NB * HE;
        float* Awr_ = g_henc[(t + 1) & 1] + dir * NB * HE;
        // 3 independent accumulator sets (one per split term) -> 6 indep chains/warp
        float aT0[2][4] = {{0,0,0,0},{0,0,0,0}};
        float aT1[2][4] = {{0,0,0,0},{0,0,0,0}};
        float aT2[2][4] = {{0,0,0,0},{0,0,0,0}};

        for (int k0 = 0; k0 < HE; k0 += 32) {
#pragma unroll
            for (int p = 0; p < 2; p++) {
                int fi = tid + p * 512;
                int r = fi >> 3, c4 = fi & 7;
                *(float4*)&sA[r * 36 + c4 * 4] = *(const float4*)&A[r * HE + k0 + c4 * 4];
            }
            {
                int hf = tid >> 8;
                int e = tid & 255;
#pragma unroll
                for (int p = 0; p < 2; p++) {
                    int idx = e + p * 256;
                    int r = idx >> 4, pi = idx & 15;
                    int nat = dir * 2048 + (r & 3) * 512 + jblk * 8 + (r >> 2);
                    unsigned v = (hf ? WLp : WHp)[(size_t)nat * (HE / 2) + (k0 >> 1) + pi];
                    (hf ? sBl : sBh)[r * 18 + pi] = v;
                }
            }
            __syncthreads();
#pragma unroll
            for (int kk = 0; kk < 2; kk++) {
                int kb = kk * 16;
                unsigned ah[4], al[4];
                float2 x;
                x = *(const float2*)&sA[r0 * 36 + kb + 2 * q];           h2_split(x.x, x.y, ah[0], al[0]);
                x = *(const float2*)&sA[(r0 + 8) * 36 + kb + 2 * q];     h2_split(x.x, x.y, ah[1], al[1]);
                x = *(const float2*)&sA[r0 * 36 + kb + 8 + 2 * q];       h2_split(x.x, x.y, ah[2], al[2]);
                x = *(const float2*)&sA[(r0 + 8) * 36 + kb + 8 + 2 * q]; h2_split(x.x, x.y, ah[3], al[3]);
#pragma unroll
                for (int nf = 0; nf < 2; nf++) {
                    int br = wc * 16 + nf * 8 + (lane >> 2);
                    unsigned bh0 = sBh[br * 18 + kk * 8 + q];
                    unsigned bh1 = sBh[br * 18 + kk * 8 + 4 + q];
                    unsigned bl0 = sBl[br * 18 + kk * 8 + q];
                    unsigned bl1 = sBl[br * 18 + kk * 8 + 4 + q];
                    mma16(aT0[nf], al[0], al[1], al[2], al[3], bh0, bh1);
                    mma16(aT1[nf], ah[0], ah[1], ah[2], ah[3], bl0, bl1);
                    mma16(aT2[nf], ah[0], ah[1], ah[2], ah[3], bh0, bh1);
                }
            }
            __syncthreads();
        }
        float acc[2][4];
#pragma unroll
        for (int nf = 0; nf < 2; nf++)
#pragma unroll
            for (int i = 0; i < 4; i++)
                acc[nf][i] = aT2[nf][i] + (aT0[nf][i] + aT1[nf][i]);
        // gate exchange (pairs share jj) + in-register pointwise
        {
            const float* Gin = g_GBUF + ((size_t)time * NB) * NGATE + p_base;
#pragma unroll
            for (int nf = 0; nf < 2; nf++) {
                float s0 = (q & 1) ? acc[nf][0] : acc[nf][2];
                float s1 = (q & 1) ? acc[nf][1] : acc[nf][3];
                float o0 = __shfl_xor_sync(0xffffffffu, s0, 1);
                float o1 = __shfl_xor_sync(0xffffffffu, s1, 1);
                float g0, g1, g2, g3;
                if (q & 1) { g0 = o0; g1 = o1; g2 = acc[nf][2]; g3 = acc[nf][3]; }
                else       { g0 = acc[nf][0]; g1 = acc[nf][1]; g2 = o0; g3 = o1; }
                int jj = wc * 4 + nf * 2 + (q >> 1);
                float4 G = *(const float4*)&Gin[(size_t)rowp * NGATE + jj * 4];
                float gi = g0 + G.x, gf = g1 + G.y, gg = g2 + G.z, go = g3 + G.w;
                float cc = creg[nf];
                cc = sigm(gf) * cc + sigm(gi) * tanhf(gg);
                float hh = sigm(go) * tanhf(cc);
                creg[nf] = cc;
                int j = jblk * 8 + jj;
                Awr_[rowp * HE + j] = hh;
                Hout[((size_t)time * NB + rowp) * HD + dir * HE + j] = hh;
            }
        }
        sync_grid();
    }
}

// ---------------- persistent decoder (512 threads, term-split accumulators) ----------------
__global__ __launch_bounds__(512) void dec_persistent(
    const float* __restrict__ bias, const float* __restrict__ wih,
    const float* __restrict__ out_w, const float* __restrict__ out_b,
    const int* __restrict__ tag_ids, float* __restrict__ prob_out)
{
    int tid = threadIdx.x, bid = blockIdx.x;
    int lane = tid & 31, w = tid >> 5;
    int wr = w & 7, wc = w >> 3;
    int q = lane & 3;
    int r0 = wr * 16 + (lane >> 2);
    int rowp = (q & 1) ? (r0 + 8) : r0;
    int j0 = bid * 8;

    g_hsum[0][bid * 1024 + tid] = g_ENC[bid * 1024 + tid];
    g_hsum[0][bid * 1024 + 512 + tid] = g_ENC[bid * 1024 + 512 + tid];
    if (bid == 0 && tid < NB) g_previdx[tid] = -1;
    if (bid == 0 && tid == 0) g_loss = 0.f;

    float creg[2], biasReg[2][4];
#pragma unroll
    for (int nf = 0; nf < 2; nf++) {
        int jj = wc * 4 + nf * 2 + (q >> 1);
        int j = j0 + jj;
        creg[nf] = g_ENC[(size_t)rowp * HD + HE + (j & (HE - 1))];
#pragma unroll
        for (int g = 0; g < 4; g++) biasReg[nf][g] = bias[g * HD + j];
    }
    sync_grid();

    __shared__ __align__(16) float sA[128 * 36];
    __shared__ unsigned sBh[32 * 18];
    __shared__ unsigned sBl[32 * 18];
    __shared__ float sh[HD];
    __shared__ float red[512];
    __shared__ float logitsS[TT];
    __shared__ float sLogZ;
    __shared__ int sArg;

    for (int t = 0; t < LSEQ; t++) {
        const float* Ain = g_hsum[t & 1];
        float* Anext = g_hsum[(t + 1) & 1];
        float aT0[2][4] = {{0,0,0,0},{0,0,0,0}};
        float aT1[2][4] = {{0,0,0,0},{0,0,0,0}};
        float aT2[2][4] = {{0,0,0,0},{0,0,0,0}};

        for (int k0 = 0; k0 < HD; k0 += 32) {
#pragma unroll
            for (int p = 0; p < 2; p++) {
                int fi = tid + p * 512;
                int r = fi >> 3, c4 = fi & 7;
                *(float4*)&sA[r * 36 + c4 * 4] = *(const float4*)&Ain[(size_t)r * HD + k0 + c4 * 4];
            }
            {
                int hf = tid >> 8;
                int e = tid & 255;
#pragma unroll
                for (int p = 0; p < 2; p++) {
                    int idx = e + p * 256;
                    int r = idx >> 4, pi = idx & 15;
                    int nat = (r & 3) * HD + j0 + (r >> 2);
                    unsigned v = (hf ? g_dL : g_dH)[(size_t)nat * (HD / 2) + (k0 >> 1) + pi];
                    (hf ? sBl : sBh)[r * 18 + pi] = v;
                }
            }
            __syncthreads();
#pragma unroll
            for (int kk = 0; kk < 2; kk++) {
                int kb = kk * 16;
                unsigned ah[4], al[4];
                float2 x;
                x = *(const float2*)&sA[r0 * 36 + kb + 2 * q];           h2_split(x.x, x.y, ah[0], al[0]);
                x = *(const float2*)&sA[(r0 + 8) * 36 + kb + 2 * q];     h2_split(x.x, x.y, ah[1], al[1]);
                x = *(const float2*)&sA[r0 * 36 + kb + 8 + 2 * q];       h2_split(x.x, x.y, ah[2], al[2]);
                x = *(const float2*)&sA[(r0 + 8) * 36 + kb + 8 + 2 * q]; h2_split(x.x, x.y, ah[3], al[3]);
#pragma unroll
                for (int nf = 0; nf < 2; nf++) {
                    int br = wc * 16 + nf * 8 + (lane >> 2);
                    unsigned bh0 = sBh[br * 18 + kk * 8 + q];
                    unsigned bh1 = sBh[br * 18 + kk * 8 + 4 + q];
                    unsigned bl0 = sBl[br * 18 + kk * 8 + q];
                    unsigned bl1 = sBl[br * 18 + kk * 8 + 4 + q];
                    mma16(aT0[nf], al[0], al[1], al[2], al[3], bh0, bh1);
                    mma16(aT1[nf], ah[0], ah[1], ah[2], ah[3], bl0, bl1);
                    mma16(aT2[nf], ah[0], ah[1], ah[2], ah[3], bh0, bh1);
                }
            }
            __syncthreads();
        }
        float acc[2][4];
#pragma unroll
        for (int nf = 0; nf < 2; nf++)
#pragma unroll
            for (int i = 0; i < 4; i++)
                acc[nf][i] = aT2[nf][i] + (aT0[nf][i] + aT1[nf][i]);
        // exchange + pointwise (+one-hot wih column, bias)
        {
            int pv = g_previdx[rowp];
#pragma unroll
            for (int nf = 0; nf < 2; nf++) {
                float s0 = (q & 1) ? acc[nf][0] : acc[nf][2];
                float s1 = (q & 1) ? acc[nf][1] : acc[nf][3];
                float o0 = __shfl_xor_sync(0xffffffffu, s0, 1);
                float o1 = __shfl_xor_sync(0xffffffffu, s1, 1);
                float g0, g1, g2, g3;
                if (q & 1) { g0 = o0; g1 = o1; g2 = acc[nf][2]; g3 = acc[nf][3]; }
                else       { g0 = acc[nf][0]; g1 = acc[nf][1]; g2 = o0; g3 = o1; }
                int jj = wc * 4 + nf * 2 + (q >> 1);
                int j = j0 + jj;
                float gi = g0 + biasReg[nf][0];
                float gf = g1 + biasReg[nf][1];
                float gg = g2 + biasReg[nf][2];
                float go = g3 + biasReg[nf][3];
                if (pv >= 0) {
                    gi += wih[(0 * HD + j) * TT + pv];
                    gf += wih[(1 * HD + j) * TT + pv];
                    gg += wih[(2 * HD + j) * TT + pv];
                    go += wih[(3 * HD + j) * TT + pv];
                }
                float cc = creg[nf];
                cc = sigm(gf) * cc + sigm(gi) * tanhf(gg);
                float hh = sigm(go) * tanhf(cc);
                creg[nf] = cc;
                g_hraw[rowp * HD + j] = hh;
                if (t + 1 < LSEQ)
                    Anext[(size_t)rowp * HD + j] = hh + g_ENC[((size_t)(t + 1) * NB + rowp) * HD + j];
            }
        }
        sync_grid();
        // logits + softmax + argmax + loss: CTA bid = batch row bid
        {
            int n = bid;
            sh[tid] = g_hraw[n * HD + tid];
            sh[tid + 512] = g_hraw[n * HD + tid + 512];
            __syncthreads();
            {
                int lj = tid & 127, quarter = tid >> 7;
                const float* wr_ = out_w + (size_t)lj * HD + quarter * 256;
                const float* hr = sh + quarter * 256;
                float s = 0.f;
#pragma unroll 8
                for (int k = 0; k < 256; k++) s += hr[k] * wr_[k];
                red[tid] = s;
            }
            __syncthreads();
            if (tid < TT)
                logitsS[tid] = red[tid] + red[tid + 128] + red[tid + 256] + red[tid + 384] + out_b[tid];
            __syncthreads();
            if (tid < 32) {
                float bv = -1e30f; int bi = 0;
#pragma unroll
                for (int p = 0; p < 4; p++) {
                    int k = tid + p * 32;
                    float v = logitsS[k];
                    if (v > bv) { bv = v; bi = k; }
                }
#pragma unroll
                for (int off = 16; off; off >>= 1) {
                    float ov = __shfl_down_sync(0xffffffffu, bv, off);
                    int   oi = __shfl_down_sync(0xffffffffu, bi, off);
                    if (ov > bv || (ov == bv && oi < bi)) { bv = ov; bi = oi; }
                }
                bv = __shfl_sync(0xffffffffu, bv, 0);
                bi = __shfl_sync(0xffffffffu, bi, 0);
                float s = 0.f;
#pragma unroll
                for (int p = 0; p < 4; p++) s += expf(logitsS[tid + p * 32] - bv);
#pragma unroll
                for (int off = 16; off; off >>= 1) s += __shfl_down_sync(0xffffffffu, s, off);
                if (tid == 0) { sLogZ = bv + logf(s); sArg = bi; }
            }
            __syncthreads();
            if (tid < TT)
                prob_out[(size_t)n * (LSEQ * TT) + t * TT + tid] = expf(logitsS[tid] - sLogZ);
            if (tid == 0) {
                g_previdx[n] = sArg;
                int tag = tag_ids[n * LSEQ + t];
                atomicAdd(&g_loss, -(logitsS[tag] - sLogZ) * (1.0f / NB));
            }
        }
        sync_grid();
    }
    if (bid == 0 && tid == 0) prob_out[(size_t)NB * LSEQ * TT] = g_loss;
}

// ---------------- launch ----------------
extern "C" void kernel_launch(void* const* d_in, const int* in_sizes, int n_in,
                              void* d_out, int out_size)
{
    const int*   input_ids = (const int*)d_in[0];
    const int*   tag_ids   = (const int*)d_in[1];
    const float* embed     = (const float*)d_in[2];
    const float* e0_wih    = (const float*)d_in[3];
    const float* e0_whh    = (const float*)d_in[4];
    const float* e0_b      = (const float*)d_in[5];
    const float* e1_wih    = (const float*)d_in[6];
    const float* e1_whh    = (const float*)d_in[7];
    const float* e1_b      = (const float*)d_in[8];
    const float* dec_wih   = (const float*)d_in[9];
    const float* dec_whh   = (const float*)d_in[10];
    const float* dec_b     = (const float*)d_in[11];
    const float* out_w     = (const float*)d_in[12];
    const float* out_b     = (const float*)d_in[13];
    float* out = (float*)d_out;
    (void)in_sizes; (void)n_in; (void)out_size;

    split_pairs<<<4096, 256>>>(e0_whh, 0, 1048576);
    split_pairs<<<4096, 256>>>(e1_whh, 1, 1048576);
    split_pairs<<<8192, 256>>>(dec_whh, 2, 2097152);
    split_pairs<<<4096, 256>>>(e0_wih, 3, 1048576);
    split_pairs<<<8192, 256>>>(e1_wih, 4, 2097152);

    dim3 ggrid(NGATE / 128, (LSEQ * NB) / 128);   // 32 x 160
    inproj_gemm<1, EMB><<<ggrid, 256>>>(e0_b, embed, input_ids);
    enc_layer_persistent<<<GRID, 512>>>(0);
    inproj_gemm<0, HD><<<ggrid, 256>>>(e1_b, embed, input_ids);
    enc_layer_persistent<<<GRID, 512>>>(1);
    dec_persistent<<<GRID, 512>>>(dec_b, dec_wih, out_w, out_b, tag_ids, out);
}